// round 10
// baseline (speedup 1.0000x reference)
#include <cuda_runtime.h>
#include <cuda_fp16.h>
#include <math.h>
#include <stdint.h>

#define S_LEN 512
#define HD    64
#define NH    16
#define NB    8
#define BH    128          // NB*NH
#define DIM   1024
#define POSJ  1024
#define SCORE_SCALE 0.07216878364870322f   // 1/sqrt(64*3)
#define PPITCH 40          // proj smem row pitch in halves (conflict-free)

// ---------------- scratch (static device globals; no runtime allocation) ----
__device__ __half g_qh[BH * S_LEN * HD];           // [b,h,s,d]
__device__ __half g_kh[BH * S_LEN * HD];
__device__ __half g_vh[BH * S_LEN * HD];
__device__ __half g_posqh[NH * POSJ * HD];         // [h,j,d]
__device__ __half g_poskh[NH * POSJ * HD];

// ---------------------------------------------------------------------------
// fp16 mma, f32 accumulate ; ldmatrix
// ---------------------------------------------------------------------------
__device__ __forceinline__ void mma_f16(float4& c, const uint32_t* a, const uint32_t* b) {
    asm volatile(
        "mma.sync.aligned.m16n8k16.row.col.f32.f16.f16.f32 "
        "{%0,%1,%2,%3}, {%4,%5,%6,%7}, {%8,%9}, {%0,%1,%2,%3};\n"
        : "+f"(c.x), "+f"(c.y), "+f"(c.z), "+f"(c.w)
        : "r"(a[0]), "r"(a[1]), "r"(a[2]), "r"(a[3]), "r"(b[0]), "r"(b[1]));
}
__device__ __forceinline__ void ldsm4(uint32_t* r, uint32_t addr) {
    asm volatile("ldmatrix.sync.aligned.m8n8.x4.shared.b16 {%0,%1,%2,%3}, [%4];"
        : "=r"(r[0]), "=r"(r[1]), "=r"(r[2]), "=r"(r[3]) : "r"(addr));
}
__device__ __forceinline__ uint32_t p2(float a, float b) {
    __half2 h = __floats2half2_rn(a, b);
    return *(uint32_t*)&h;
}

// ---------------------------------------------------------------------------
// fp16 projection GEMM: C[m,n] = sum_k A[m,k]*W[n,k] + bias[n]  -> __half out
// Block 128x128, BK=32, 128 threads = 4 warps (2m x 2n), warp tile 64x64.
// ldmatrix.x4 fragment loads.
// grid.z selects (W, bias, out):
//   MODE 0 (token, A=x): z=0 Q, z=1 K, z=2 V        -> [b,h,s,d]
//   MODE 1 (pos, A=rel): z=0 posQ(Wq), z=1 posK(Wk) -> [h,j,d]
// ---------------------------------------------------------------------------
template <int MODE>
__global__ void __launch_bounds__(128) proj_f16(const float* __restrict__ A,
                                                const float* __restrict__ W0,
                                                const float* __restrict__ W1,
                                                const float* __restrict__ W2,
                                                const float* __restrict__ bias0,
                                                const float* __restrict__ bias1,
                                                const float* __restrict__ bias2)
{
    const int z = blockIdx.z;
    const float* W    = (z == 0) ? W0 : (z == 1) ? W1 : W2;
    const float* bias = (z == 0) ? bias0 : (z == 1) ? bias1 : bias2;
    __half* out = (MODE == 0) ? ((z == 0) ? g_qh : (z == 1) ? g_kh : g_vh)
                              : ((z == 0) ? g_posqh : g_poskh);

    __shared__ __half As[128 * PPITCH];
    __shared__ __half Bs[128 * PPITCH];

    const int tid  = threadIdx.x;
    const int warp = tid >> 5, lane = tid & 31;
    const int wm = warp >> 1, wn = warp & 1;
    const int g  = lane >> 2, tg = lane & 3;
    const int bm = blockIdx.y, bn = blockIdx.x;

    // ldmatrix lane address components
    const int sub = lane >> 3, lr8 = lane & 7;
    const uint32_t As_base = (uint32_t)__cvta_generic_to_shared(As);
    const uint32_t Bs_base = (uint32_t)__cvta_generic_to_shared(Bs);
    // A: sub0: rows,k0  sub1: rows+8,k0  sub2: rows,k8  sub3: rows+8,k8
    const int a_row = wm * 64 + lr8 + ((sub & 1) << 3);
    const int a_col = (sub & 2) << 2;
    // B: sub0: n(fp),k0  sub1: n(fp),k8  sub2: n(fp+1),k0  sub3: n(fp+1),k8
    const int b_row = wn * 64 + ((sub >> 1) << 3) + lr8;
    const int b_col = (sub & 1) << 3;

    // global load: each thread owns one 32-float row slice of each tile
    const int lrow = tid;
    const float* Ap = A + (size_t)(bm * 128 + lrow) * DIM;
    const float* Wp = W + (size_t)(bn * 128 + lrow) * DIM;

    uint4 ua[4], ub[4];
    {
#pragma unroll
        for (int i = 0; i < 4; i++) {
            float4 f0 = ((const float4*)Ap)[2 * i];
            float4 f1 = ((const float4*)Ap)[2 * i + 1];
            ua[i].x = p2(f0.x, f0.y); ua[i].y = p2(f0.z, f0.w);
            ua[i].z = p2(f1.x, f1.y); ua[i].w = p2(f1.z, f1.w);
            float4 g0 = ((const float4*)Wp)[2 * i];
            float4 g1 = ((const float4*)Wp)[2 * i + 1];
            ub[i].x = p2(g0.x, g0.y); ub[i].y = p2(g0.z, g0.w);
            ub[i].z = p2(g1.x, g1.y); ub[i].w = p2(g1.z, g1.w);
        }
    }

    float4 c[4][8];
#pragma unroll
    for (int t = 0; t < 4; t++)
#pragma unroll
        for (int f = 0; f < 8; f++) c[t][f] = make_float4(0.f, 0.f, 0.f, 0.f);

    for (int kt = 0; kt < DIM; kt += 32) {
        __syncthreads();
        {
            uint4* ad = (uint4*)(As + lrow * PPITCH);
            uint4* bd = (uint4*)(Bs + lrow * PPITCH);
#pragma unroll
            for (int i = 0; i < 4; i++) { ad[i] = ua[i]; bd[i] = ub[i]; }
        }
        __syncthreads();
        if (kt + 32 < DIM) {
            const float4* an = (const float4*)(Ap + kt + 32);
            const float4* wn4 = (const float4*)(Wp + kt + 32);
#pragma unroll
            for (int i = 0; i < 4; i++) {
                float4 f0 = an[2 * i], f1 = an[2 * i + 1];
                ua[i].x = p2(f0.x, f0.y); ua[i].y = p2(f0.z, f0.w);
                ua[i].z = p2(f1.x, f1.y); ua[i].w = p2(f1.z, f1.w);
                float4 g0 = wn4[2 * i], g1 = wn4[2 * i + 1];
                ub[i].x = p2(g0.x, g0.y); ub[i].y = p2(g0.z, g0.w);
                ub[i].z = p2(g1.x, g1.y); ub[i].w = p2(g1.z, g1.w);
            }
        }
#pragma unroll
        for (int k16 = 0; k16 < 2; k16++) {
            const int kb = k16 * 16;
            uint32_t a[4][4], b[8][2];
#pragma unroll
            for (int t = 0; t < 4; t++)
                ldsm4(a[t], As_base + (uint32_t)(((a_row + t * 16) * PPITCH) + kb + a_col) * 2);
#pragma unroll
            for (int fp = 0; fp < 8; fp += 2) {
                uint32_t r[4];
                ldsm4(r, Bs_base + (uint32_t)(((b_row + fp * 8) * PPITCH) + kb + b_col) * 2);
                b[fp][0] = r[0]; b[fp][1] = r[1];
                b[fp + 1][0] = r[2]; b[fp + 1][1] = r[3];
            }
#pragma unroll
            for (int t = 0; t < 4; t++)
#pragma unroll
                for (int f = 0; f < 8; f++)
                    mma_f16(c[t][f], a[t], b[f]);
        }
    }

    // epilogue: add bias, convert to half, store scattered per layout
#pragma unroll
    for (int t = 0; t < 4; t++) {
        const int row0 = bm * 128 + wm * 64 + t * 16 + g;
#pragma unroll
        for (int f = 0; f < 8; f++) {
            const int col = bn * 128 + wn * 64 + f * 8 + 2 * tg;
            const float b0 = bias[col], b1 = bias[col + 1];
            __half2 h0 = __floats2half2_rn(c[t][f].x + b0, c[t][f].y + b1);
            __half2 h1 = __floats2half2_rn(c[t][f].z + b0, c[t][f].w + b1);
            const int h = col >> 6, d = col & 63;
            if (MODE == 0) {
                const int bb0 = row0 >> 9, s0 = row0 & 511;
                *(__half2*)(out + ((size_t)(bb0 * NH + h) * S_LEN + s0) * HD + d) = h0;
                const int r1 = row0 + 8;
                const int bb1 = r1 >> 9, s1 = r1 & 511;
                *(__half2*)(out + ((size_t)(bb1 * NH + h) * S_LEN + s1) * HD + d) = h1;
            } else {
                *(__half2*)(out + ((size_t)h * POSJ + row0) * HD + d) = h0;
                *(__half2*)(out + ((size_t)h * POSJ + row0 + 8) * HD + d) = h1;
            }
        }
    }
}

// ---------------------------------------------------------------------------
// Fused fp16 tensor-core attention with in-tile c2p/p2c band GEMMs.
// (unchanged from 526us passing kernel)
// ---------------------------------------------------------------------------
#define SM_QH    0
#define SM_KSH   9216
#define SM_VTH   18432
#define SM_BAND  27648
#define SM_PROD  46080
#define SM_PS    79872
#define SM_MASK  89088
#define ATTN2_SMEM (89088 + 2048)

__global__ void __launch_bounds__(128) attn2_kernel(const float* __restrict__ mask,
                                                    float* __restrict__ out)
{
    extern __shared__ char smraw[];
    __half* Qh   = (__half*)(smraw + SM_QH);     // [64][72]
    __half* Ksh  = (__half*)(smraw + SM_KSH);    // [64][72]
    __half* Vth  = (__half*)(smraw + SM_VTH);    // [64][72] (V transposed: [d][k])
    __half* Bandh= (__half*)(smraw + SM_BAND);   // [128][72]
    float*  Prod = (float*)(smraw + SM_PROD);    // [64][132]
    __half* Ps   = (__half*)(smraw + SM_PS);     // [64][72]
    float*  Mf   = (float*)(smraw + SM_MASK);    // [512]

    const int tid = threadIdx.x;
    const int w = tid >> 5, lane = tid & 31;
    const int g = lane >> 2, tg = lane & 3;
    const int bh = blockIdx.y;
    const int b = bh >> 4, h = bh & 15;
    const int q0 = blockIdx.x << 6;

    // ---- prologue: load Q tile + mask row -----------------------------------
    {
        const int row = tid >> 1, seg = tid & 1;
        const uint4* src = (const uint4*)(g_qh + ((size_t)bh * S_LEN + q0 + row) * HD + seg * 32);
        uint4* dst = (uint4*)(Qh + row * 72 + seg * 32);
#pragma unroll
        for (int i = 0; i < 4; i++) dst[i] = src[i];
        *(float4*)(Mf + tid * 4) = *(const float4*)(mask + b * S_LEN + tid * 4);
    }

    const int qq = 16 * w + g;            // this thread's base S row (tile-local)

    float4 sfr[8], acc[8];
    float m0 = -1e30f, m1 = -1e30f, l0 = 0.f, l1 = 0.f;
#pragma unroll
    for (int f = 0; f < 8; f++) acc[f] = make_float4(0.f, 0.f, 0.f, 0.f);

    for (int kt = 0; kt < 8; kt++) {
        const int k0 = kt << 6;
        __syncthreads();

        // ---- loads: K tile, V transposed, posK band -------------------------
        {
            const int row = tid >> 1, seg = tid & 1;
            const uint4* ks = (const uint4*)(g_kh + ((size_t)bh * S_LEN + k0 + row) * HD + seg * 32);
            uint4* kd = (uint4*)(Ksh + row * 72 + seg * 32);
#pragma unroll
            for (int i = 0; i < 4; i++) kd[i] = ks[i];

            const __half2* vs = (const __half2*)(g_vh + ((size_t)bh * S_LEN + k0 + row) * HD + seg * 32);
#pragma unroll
            for (int i = 0; i < 16; i++) {
                __half2 v = vs[i];
                const int d = seg * 32 + 2 * i;
                Vth[d * 72 + row] = __low2half(v);
                Vth[(d + 1) * 72 + row] = __high2half(v);
            }
            // posK band: row r = tid, j = q0 - k0 + 449 + r, clamped
            int j = q0 - k0 + 449 + tid;
            j = j < 0 ? 0 : (j > 1023 ? 1023 : j);
            const uint4* bs = (const uint4*)(g_poskh + ((size_t)h * POSJ + j) * HD);
            uint4* bd = (uint4*)(Bandh + tid * 72);
#pragma unroll
            for (int i = 0; i < 8; i++) bd[i] = bs[i];
        }
        __syncthreads();

        // ---- S = Q K^T ------------------------------------------------------
#pragma unroll
        for (int f = 0; f < 8; f++) sfr[f] = make_float4(0.f, 0.f, 0.f, 0.f);
#pragma unroll
        for (int c = 0; c < 4; c++) {
            uint32_t a[4];
            const __half* qr = Qh + qq * 72 + 16 * c + 2 * tg;
            a[0] = *(const uint32_t*)qr;
            a[1] = *(const uint32_t*)(qr + 8 * 72);
            a[2] = *(const uint32_t*)(qr + 8);
            a[3] = *(const uint32_t*)(qr + 8 * 72 + 8);
#pragma unroll
            for (int f = 0; f < 8; f++) {
                uint32_t bb[2];
                const __half* kb = Ksh + (8 * f + g) * 72 + 16 * c + 2 * tg;
                bb[0] = *(const uint32_t*)kb;
                bb[1] = *(const uint32_t*)(kb + 8);
                mma_f16(sfr[f], a, bb);
            }
        }

        // ---- C2P = Q @ posK_band^T -> Prod [64][128] ------------------------
#pragma unroll
        for (int pass = 0; pass < 2; pass++) {
            float4 t[8];
#pragma unroll
            for (int f = 0; f < 8; f++) t[f] = make_float4(0.f, 0.f, 0.f, 0.f);
#pragma unroll
            for (int c = 0; c < 4; c++) {
                uint32_t a[4];
                const __half* qr = Qh + qq * 72 + 16 * c + 2 * tg;
                a[0] = *(const uint32_t*)qr;
                a[1] = *(const uint32_t*)(qr + 8 * 72);
                a[2] = *(const uint32_t*)(qr + 8);
                a[3] = *(const uint32_t*)(qr + 8 * 72 + 8);
#pragma unroll
                for (int f = 0; f < 8; f++) {
                    uint32_t bb[2];
                    const __half* pb = Bandh + (64 * pass + 8 * f + g) * 72 + 16 * c + 2 * tg;
                    bb[0] = *(const uint32_t*)pb;
                    bb[1] = *(const uint32_t*)(pb + 8);
                    mma_f16(t[f], a, bb);
                }
            }
#pragma unroll
            for (int f = 0; f < 8; f++) {
                float* p0 = Prod + qq * 132 + 64 * pass + 8 * f + 2 * tg;
                p0[0] = t[f].x; p0[1] = t[f].y;
                p0[8 * 132] = t[f].z; p0[8 * 132 + 1] = t[f].w;
            }
        }
        __syncthreads();

        // ---- gather c2p into S (Prod[q][q-k+63]); load posQ band ------------
#pragma unroll
        for (int f = 0; f < 8; f++) {
            const int kk = 8 * f + 2 * tg;
            sfr[f].x += Prod[qq * 132 + qq - kk + 63];
            sfr[f].y += Prod[qq * 132 + qq - kk + 62];
            sfr[f].z += Prod[(qq + 8) * 132 + qq - kk + 71];
            sfr[f].w += Prod[(qq + 8) * 132 + qq - kk + 70];
        }
        {
            // p2c band uses the SAME index mapping: j = q0 - k0 + 449 + r
            int j = q0 - k0 + 449 + tid;
            j = j < 0 ? 0 : (j > 1023 ? 1023 : j);
            const uint4* bs = (const uint4*)(g_posqh + ((size_t)h * POSJ + j) * HD);
            uint4* bd = (uint4*)(Bandh + tid * 72);
#pragma unroll
            for (int i = 0; i < 8; i++) bd[i] = bs[i];
        }
        __syncthreads();

        // ---- P2C = K @ posQ_band^T -> Prod ----------------------------------
#pragma unroll
        for (int pass = 0; pass < 2; pass++) {
            float4 t[8];
#pragma unroll
            for (int f = 0; f < 8; f++) t[f] = make_float4(0.f, 0.f, 0.f, 0.f);
#pragma unroll
            for (int c = 0; c < 4; c++) {
                uint32_t a[4];
                const __half* kr = Ksh + qq * 72 + 16 * c + 2 * tg;
                a[0] = *(const uint32_t*)kr;
                a[1] = *(const uint32_t*)(kr + 8 * 72);
                a[2] = *(const uint32_t*)(kr + 8);
                a[3] = *(const uint32_t*)(kr + 8 * 72 + 8);
#pragma unroll
                for (int f = 0; f < 8; f++) {
                    uint32_t bb[2];
                    const __half* pb = Bandh + (64 * pass + 8 * f + g) * 72 + 16 * c + 2 * tg;
                    bb[0] = *(const uint32_t*)pb;
                    bb[1] = *(const uint32_t*)(pb + 8);
                    mma_f16(t[f], a, bb);
                }
            }
#pragma unroll
            for (int f = 0; f < 8; f++) {
                float* p0 = Prod + qq * 132 + 64 * pass + 8 * f + 2 * tg;
                p0[0] = t[f].x; p0[1] = t[f].y;
                p0[8 * 132] = t[f].z; p0[8 * 132 + 1] = t[f].w;
            }
        }
        __syncthreads();

        // ---- gather p2c (Prod[k][q-k+63]), scale + mask ---------------------
#pragma unroll
        for (int f = 0; f < 8; f++) {
            const int kk = 8 * f + 2 * tg;
            sfr[f].x += Prod[kk * 132 + qq - kk + 63];
            sfr[f].y += Prod[(kk + 1) * 132 + qq - kk + 62];
            sfr[f].z += Prod[kk * 132 + qq - kk + 71];
            sfr[f].w += Prod[(kk + 1) * 132 + qq - kk + 70];
            const float mk0 = Mf[k0 + kk], mk1 = Mf[k0 + kk + 1];
            sfr[f].x = sfr[f].x * SCORE_SCALE + mk0;
            sfr[f].y = sfr[f].y * SCORE_SCALE + mk1;
            sfr[f].z = sfr[f].z * SCORE_SCALE + mk0;
            sfr[f].w = sfr[f].w * SCORE_SCALE + mk1;
        }

        // ---- online softmax -------------------------------------------------
        float r0 = -1e30f, r1 = -1e30f;
#pragma unroll
        for (int f = 0; f < 8; f++) {
            r0 = fmaxf(r0, fmaxf(sfr[f].x, sfr[f].y));
            r1 = fmaxf(r1, fmaxf(sfr[f].z, sfr[f].w));
        }
        r0 = fmaxf(r0, __shfl_xor_sync(0xffffffffu, r0, 1));
        r0 = fmaxf(r0, __shfl_xor_sync(0xffffffffu, r0, 2));
        r1 = fmaxf(r1, __shfl_xor_sync(0xffffffffu, r1, 1));
        r1 = fmaxf(r1, __shfl_xor_sync(0xffffffffu, r1, 2));
        const float nm0 = fmaxf(m0, r0), nm1 = fmaxf(m1, r1);
        const float sc0 = __expf(m0 - nm0), sc1 = __expf(m1 - nm1);
        float rs0 = 0.f, rs1 = 0.f;
#pragma unroll
        for (int f = 0; f < 8; f++) {
            const float px = __expf(sfr[f].x - nm0);
            const float py = __expf(sfr[f].y - nm0);
            const float pz = __expf(sfr[f].z - nm1);
            const float pw = __expf(sfr[f].w - nm1);
            rs0 += px + py; rs1 += pz + pw;
            *(__half2*)(Ps + qq * 72 + 8 * f + 2 * tg) = __floats2half2_rn(px, py);
            *(__half2*)(Ps + (qq + 8) * 72 + 8 * f + 2 * tg) = __floats2half2_rn(pz, pw);
            acc[f].x *= sc0; acc[f].y *= sc0;
            acc[f].z *= sc1; acc[f].w *= sc1;
        }
        rs0 += __shfl_xor_sync(0xffffffffu, rs0, 1);
        rs0 += __shfl_xor_sync(0xffffffffu, rs0, 2);
        rs1 += __shfl_xor_sync(0xffffffffu, rs1, 1);
        rs1 += __shfl_xor_sync(0xffffffffu, rs1, 2);
        l0 = l0 * sc0 + rs0;
        l1 = l1 * sc1 + rs1;
        m0 = nm0; m1 = nm1;

        __syncwarp();   // Ps rows are warp-local; warp-level visibility suffices

        // ---- PV: acc += P @ V ----------------------------------------------
#pragma unroll
        for (int c = 0; c < 4; c++) {
            uint32_t a[4];
            const __half* pr = Ps + qq * 72 + 16 * c + 2 * tg;
            a[0] = *(const uint32_t*)pr;
            a[1] = *(const uint32_t*)(pr + 8 * 72);
            a[2] = *(const uint32_t*)(pr + 8);
            a[3] = *(const uint32_t*)(pr + 8 * 72 + 8);
#pragma unroll
            for (int f = 0; f < 8; f++) {
                uint32_t bb[2];
                const __half* vb = Vth + (8 * f + g) * 72 + 16 * c + 2 * tg;
                bb[0] = *(const uint32_t*)vb;
                bb[1] = *(const uint32_t*)(vb + 8);
                mma_f16(acc[f], a, bb);
            }
        }
    }

    // ---- epilogue: normalize, write [b, s, h*64+d] as f32 -------------------
    const float inv0 = 1.0f / l0, inv1 = 1.0f / l1;
    float* orow0 = out + ((size_t)b * S_LEN + q0 + qq) * DIM + h * HD;
    float* orow1 = orow0 + 8 * DIM;
#pragma unroll
    for (int f = 0; f < 8; f++) {
        const int col = 8 * f + 2 * tg;
        *(float2*)(orow0 + col) = make_float2(acc[f].x * inv0, acc[f].y * inv0);
        *(float2*)(orow1 + col) = make_float2(acc[f].z * inv1, acc[f].w * inv1);
    }
}

// ---------------------------------------------------------------------------
extern "C" void kernel_launch(void* const* d_in, const int* in_sizes, int n_in,
                              void* d_out, int out_size)
{
    const float* x    = (const float*)d_in[0];
    const float* rel  = (const float*)d_in[1];
    const float* mask = (const float*)d_in[2];
    const float* Wq   = (const float*)d_in[3];
    const float* bq   = (const float*)d_in[4];
    const float* Wk   = (const float*)d_in[5];
    const float* bk   = (const float*)d_in[6];
    const float* Wv   = (const float*)d_in[7];
    const float* bv   = (const float*)d_in[8];
    float* out = (float*)d_out;

    // merged fp16 projections: token (Q,K,V) and pos (posQ, posK)
    proj_f16<0><<<dim3(8, 32, 3), dim3(128)>>>(x, Wq, Wk, Wv, bq, bk, bv);
    proj_f16<1><<<dim3(8, 8, 2), dim3(128)>>>(rel, Wq, Wk, Wk, bq, bk, bk);

    // fused fp16 attention with in-tile c2p/p2c
    cudaFuncSetAttribute(attn2_kernel, cudaFuncAttributeMaxDynamicSharedMemorySize,
                         ATTN2_SMEM);
    attn2_kernel<<<dim3(8, BH), dim3(128), ATTN2_SMEM>>>(mask, out);
}

// round 13
// speedup vs baseline: 1.1897x; 1.1897x over previous
#include <cuda_runtime.h>
#include <cuda_fp16.h>
#include <math.h>
#include <stdint.h>

#define S_LEN 512
#define HD    64
#define NH    16
#define NB    8
#define BH    128          // NB*NH
#define DIM   1024
#define POSJ  1024
#define SCORE_SCALE 0.07216878364870322f   // 1/sqrt(64*3)
#define QPITCH 40          // proj smem row pitch in halves (conflict-free)
#define NSTAGE (DIM / 32)  // 32 stages of BK=32 cover the full K reduction

// ---------------- scratch (static device globals; no runtime allocation) ----
__device__ __half g_qh[BH * S_LEN * HD];           // [b,h,s,d]
__device__ __half g_kh[BH * S_LEN * HD];
__device__ __half g_vh[BH * S_LEN * HD];
__device__ __half g_posqh[NH * POSJ * HD];         // [h,j,d]
__device__ __half g_poskh[NH * POSJ * HD];
// pre-converted fp16 inputs
__device__ __half g_xh[NB * S_LEN * DIM];
__device__ __half g_wqh[DIM * DIM];
__device__ __half g_wkh[DIM * DIM];
__device__ __half g_wvh[DIM * DIM];
__device__ __half g_relh[POSJ * DIM];

// ---------------------------------------------------------------------------
// helpers
// ---------------------------------------------------------------------------
__device__ __forceinline__ void mma_f16(float4& c, const uint32_t* a, const uint32_t* b) {
    asm volatile(
        "mma.sync.aligned.m16n8k16.row.col.f32.f16.f16.f32 "
        "{%0,%1,%2,%3}, {%4,%5,%6,%7}, {%8,%9}, {%0,%1,%2,%3};\n"
        : "+f"(c.x), "+f"(c.y), "+f"(c.z), "+f"(c.w)
        : "r"(a[0]), "r"(a[1]), "r"(a[2]), "r"(a[3]), "r"(b[0]), "r"(b[1]));
}
__device__ __forceinline__ uint32_t p2(float a, float b) {
    __half2 h = __floats2half2_rn(a, b);
    return *(uint32_t*)&h;
}
__device__ __forceinline__ void cpa16(uint32_t dst, const void* src) {
    asm volatile("cp.async.ca.shared.global [%0], [%1], 16;" :: "r"(dst), "l"(src) : "memory");
}

// ---------------------------------------------------------------------------
// f32 -> f16 bulk convert (8 floats / thread)
// ---------------------------------------------------------------------------
__global__ void __launch_bounds__(256) cvt_f16(const float* __restrict__ src,
                                               __half* __restrict__ dst, int n8)
{
    const int i = blockIdx.x * blockDim.x + threadIdx.x;
    if (i < n8) {
        const float4 f0 = ((const float4*)src)[2 * i];
        const float4 f1 = ((const float4*)src)[2 * i + 1];
        uint4 u;
        u.x = p2(f0.x, f0.y); u.y = p2(f0.z, f0.w);
        u.z = p2(f1.x, f1.y); u.w = p2(f1.z, f1.w);
        ((uint4*)dst)[i] = u;
    }
}

// ---------------------------------------------------------------------------
// fp16 projection GEMM (fp16 inputs): C = A * W^T + bias -> __half out
// Block 128x128, BK=32 x 32 stages (full K=1024), 128 threads = 4 warps
// (2m x 2n), warp tile 64x64. cp.async double-buffered staging.
//   MODE 0 (token, A=g_xh): z=0 Q, z=1 K, z=2 V      -> [b,h,s,d]
//   MODE 1 (pos, A=g_relh): z=0 posQ, z=1 posK       -> [h,j,d]
// ---------------------------------------------------------------------------
template <int MODE>
__global__ void __launch_bounds__(128) proj_h(const __half* __restrict__ A,
                                              const __half* __restrict__ W0,
                                              const __half* __restrict__ W1,
                                              const __half* __restrict__ W2,
                                              const float* __restrict__ bias0,
                                              const float* __restrict__ bias1,
                                              const float* __restrict__ bias2)
{
    const int z = blockIdx.z;
    const __half* W   = (z == 0) ? W0 : (z == 1) ? W1 : W2;
    const float* bias = (z == 0) ? bias0 : (z == 1) ? bias1 : bias2;
    __half* out = (MODE == 0) ? ((z == 0) ? g_qh : (z == 1) ? g_kh : g_vh)
                              : ((z == 0) ? g_posqh : g_poskh);

    __shared__ __half As[2][128 * QPITCH];
    __shared__ __half Bs[2][128 * QPITCH];

    const int tid  = threadIdx.x;
    const int warp = tid >> 5, lane = tid & 31;
    const int wm = warp >> 1, wn = warp & 1;
    const int g  = lane >> 2, tg = lane & 3;
    const int bm = blockIdx.y, bn = blockIdx.x;

    const __half* Ap = A + (size_t)(bm * 128 + tid) * DIM;
    const __half* Wp = W + (size_t)(bn * 128 + tid) * DIM;
    const uint32_t a0 = (uint32_t)__cvta_generic_to_shared(&As[0][tid * QPITCH]);
    const uint32_t b0 = (uint32_t)__cvta_generic_to_shared(&Bs[0][tid * QPITCH]);
    const uint32_t stage_bytes = 128 * QPITCH * 2;

    float4 c[4][8];
#pragma unroll
    for (int t = 0; t < 4; t++)
#pragma unroll
        for (int f = 0; f < 8; f++) c[t][f] = make_float4(0.f, 0.f, 0.f, 0.f);

    // stage 0 load
    {
#pragma unroll
        for (int ch = 0; ch < 4; ch++) {
            cpa16(a0 + ch * 16, Ap + ch * 8);
            cpa16(b0 + ch * 16, Wp + ch * 8);
        }
        asm volatile("cp.async.commit_group;" ::: "memory");
    }

    for (int s = 0; s < NSTAGE; s++) {
        const int p = s & 1;
        if (s < NSTAGE - 1) {
            const uint32_t ao = a0 + (uint32_t)((s + 1) & 1) * stage_bytes;
            const uint32_t bo = b0 + (uint32_t)((s + 1) & 1) * stage_bytes;
            const __half* as = Ap + (s + 1) * 32;
            const __half* ws = Wp + (s + 1) * 32;
#pragma unroll
            for (int ch = 0; ch < 4; ch++) {
                cpa16(ao + ch * 16, as + ch * 8);
                cpa16(bo + ch * 16, ws + ch * 8);
            }
            asm volatile("cp.async.commit_group;" ::: "memory");
            asm volatile("cp.async.wait_group 1;" ::: "memory");
        } else {
            asm volatile("cp.async.wait_group 0;" ::: "memory");
        }
        __syncthreads();

#pragma unroll
        for (int k16 = 0; k16 < 2; k16++) {
            const int kb = k16 * 16 + 2 * tg;
            uint32_t a[4][4], b[8][2];
#pragma unroll
            for (int t = 0; t < 4; t++) {
                const __half* ar = &As[p][(wm * 64 + t * 16 + g) * QPITCH + kb];
                a[t][0] = *(const uint32_t*)ar;
                a[t][1] = *(const uint32_t*)(ar + 8 * QPITCH);
                a[t][2] = *(const uint32_t*)(ar + 8);
                a[t][3] = *(const uint32_t*)(ar + 8 * QPITCH + 8);
            }
#pragma unroll
            for (int f = 0; f < 8; f++) {
                const __half* br = &Bs[p][(wn * 64 + f * 8 + g) * QPITCH + kb];
                b[f][0] = *(const uint32_t*)br;
                b[f][1] = *(const uint32_t*)(br + 8);
            }
#pragma unroll
            for (int t = 0; t < 4; t++)
#pragma unroll
                for (int f = 0; f < 8; f++)
                    mma_f16(c[t][f], a[t], b[f]);
        }
        __syncthreads();
    }

    // epilogue: add bias, convert to half, store scattered per layout
#pragma unroll
    for (int t = 0; t < 4; t++) {
        const int row0 = bm * 128 + wm * 64 + t * 16 + g;
#pragma unroll
        for (int f = 0; f < 8; f++) {
            const int col = bn * 128 + wn * 64 + f * 8 + 2 * tg;
            const float bb0 = bias[col], bb1 = bias[col + 1];
            __half2 h0 = __floats2half2_rn(c[t][f].x + bb0, c[t][f].y + bb1);
            __half2 h1 = __floats2half2_rn(c[t][f].z + bb0, c[t][f].w + bb1);
            const int h = col >> 6, d = col & 63;
            if (MODE == 0) {
                const int bi0 = row0 >> 9, s0 = row0 & 511;
                *(__half2*)(out + ((size_t)(bi0 * NH + h) * S_LEN + s0) * HD + d) = h0;
                const int r1 = row0 + 8;
                const int bi1 = r1 >> 9, s1 = r1 & 511;
                *(__half2*)(out + ((size_t)(bi1 * NH + h) * S_LEN + s1) * HD + d) = h1;
            } else {
                *(__half2*)(out + ((size_t)h * POSJ + row0) * HD + d) = h0;
                *(__half2*)(out + ((size_t)h * POSJ + row0 + 8) * HD + d) = h1;
            }
        }
    }
}

// ---------------------------------------------------------------------------
// Fused fp16 tensor-core attention with in-tile c2p/p2c band GEMMs.
// (byte-identical to the 526us passing kernel)
// ---------------------------------------------------------------------------
#define SM_QH    0
#define SM_KSH   9216
#define SM_VTH   18432
#define SM_BAND  27648
#define SM_PROD  46080
#define SM_PS    79872
#define SM_MASK  89088
#define ATTN2_SMEM (89088 + 2048)

__global__ void __launch_bounds__(128) attn2_kernel(const float* __restrict__ mask,
                                                    float* __restrict__ out)
{
    extern __shared__ char smraw[];
    __half* Qh   = (__half*)(smraw + SM_QH);     // [64][72]
    __half* Ksh  = (__half*)(smraw + SM_KSH);    // [64][72]
    __half* Vth  = (__half*)(smraw + SM_VTH);    // [64][72] (V transposed: [d][k])
    __half* Bandh= (__half*)(smraw + SM_BAND);   // [128][72]
    float*  Prod = (float*)(smraw + SM_PROD);    // [64][132]
    __half* Ps   = (__half*)(smraw + SM_PS);     // [64][72]
    float*  Mf   = (float*)(smraw + SM_MASK);    // [512]

    const int tid = threadIdx.x;
    const int w = tid >> 5, lane = tid & 31;
    const int g = lane >> 2, tg = lane & 3;
    const int bh = blockIdx.y;
    const int b = bh >> 4, h = bh & 15;
    const int q0 = blockIdx.x << 6;

    {
        const int row = tid >> 1, seg = tid & 1;
        const uint4* src = (const uint4*)(g_qh + ((size_t)bh * S_LEN + q0 + row) * HD + seg * 32);
        uint4* dst = (uint4*)(Qh + row * 72 + seg * 32);
#pragma unroll
        for (int i = 0; i < 4; i++) dst[i] = src[i];
        *(float4*)(Mf + tid * 4) = *(const float4*)(mask + b * S_LEN + tid * 4);
    }

    const int qq = 16 * w + g;

    float4 sfr[8], acc[8];
    float m0 = -1e30f, m1 = -1e30f, l0 = 0.f, l1 = 0.f;
#pragma unroll
    for (int f = 0; f < 8; f++) acc[f] = make_float4(0.f, 0.f, 0.f, 0.f);

    for (int kt = 0; kt < 8; kt++) {
        const int k0 = kt << 6;
        __syncthreads();

        {
            const int row = tid >> 1, seg = tid & 1;
            const uint4* ks = (const uint4*)(g_kh + ((size_t)bh * S_LEN + k0 + row) * HD + seg * 32);
            uint4* kd = (uint4*)(Ksh + row * 72 + seg * 32);
#pragma unroll
            for (int i = 0; i < 4; i++) kd[i] = ks[i];

            const __half2* vs = (const __half2*)(g_vh + ((size_t)bh * S_LEN + k0 + row) * HD + seg * 32);
#pragma unroll
            for (int i = 0; i < 16; i++) {
                __half2 v = vs[i];
                const int d = seg * 32 + 2 * i;
                Vth[d * 72 + row] = __low2half(v);
                Vth[(d + 1) * 72 + row] = __high2half(v);
            }
            int j = q0 - k0 + 449 + tid;
            j = j < 0 ? 0 : (j > 1023 ? 1023 : j);
            const uint4* bs = (const uint4*)(g_poskh + ((size_t)h * POSJ + j) * HD);
            uint4* bd = (uint4*)(Bandh + tid * 72);
#pragma unroll
            for (int i = 0; i < 8; i++) bd[i] = bs[i];
        }
        __syncthreads();

#pragma unroll
        for (int f = 0; f < 8; f++) sfr[f] = make_float4(0.f, 0.f, 0.f, 0.f);
#pragma unroll
        for (int c = 0; c < 4; c++) {
            uint32_t a[4];
            const __half* qr = Qh + qq * 72 + 16 * c + 2 * tg;
            a[0] = *(const uint32_t*)qr;
            a[1] = *(const uint32_t*)(qr + 8 * 72);
            a[2] = *(const uint32_t*)(qr + 8);
            a[3] = *(const uint32_t*)(qr + 8 * 72 + 8);
#pragma unroll
            for (int f = 0; f < 8; f++) {
                uint32_t bb[2];
                const __half* kb = Ksh + (8 * f + g) * 72 + 16 * c + 2 * tg;
                bb[0] = *(const uint32_t*)kb;
                bb[1] = *(const uint32_t*)(kb + 8);
                mma_f16(sfr[f], a, bb);
            }
        }

#pragma unroll
        for (int pass = 0; pass < 2; pass++) {
            float4 t[8];
#pragma unroll
            for (int f = 0; f < 8; f++) t[f] = make_float4(0.f, 0.f, 0.f, 0.f);
#pragma unroll
            for (int c = 0; c < 4; c++) {
                uint32_t a[4];
                const __half* qr = Qh + qq * 72 + 16 * c + 2 * tg;
                a[0] = *(const uint32_t*)qr;
                a[1] = *(const uint32_t*)(qr + 8 * 72);
                a[2] = *(const uint32_t*)(qr + 8);
                a[3] = *(const uint32_t*)(qr + 8 * 72 + 8);
#pragma unroll
                for (int f = 0; f < 8; f++) {
                    uint32_t bb[2];
                    const __half* pb = Bandh + (64 * pass + 8 * f + g) * 72 + 16 * c + 2 * tg;
                    bb[0] = *(const uint32_t*)pb;
                    bb[1] = *(const uint32_t*)(pb + 8);
                    mma_f16(t[f], a, bb);
                }
            }
#pragma unroll
            for (int f = 0; f < 8; f++) {
                float* p0 = Prod + qq * 132 + 64 * pass + 8 * f + 2 * tg;
                p0[0] = t[f].x; p0[1] = t[f].y;
                p0[8 * 132] = t[f].z; p0[8 * 132 + 1] = t[f].w;
            }
        }
        __syncthreads();

#pragma unroll
        for (int f = 0; f < 8; f++) {
            const int kk = 8 * f + 2 * tg;
            sfr[f].x += Prod[qq * 132 + qq - kk + 63];
            sfr[f].y += Prod[qq * 132 + qq - kk + 62];
            sfr[f].z += Prod[(qq + 8) * 132 + qq - kk + 71];
            sfr[f].w += Prod[(qq + 8) * 132 + qq - kk + 70];
        }
        {
            int j = q0 - k0 + 449 + tid;
            j = j < 0 ? 0 : (j > 1023 ? 1023 : j);
            const uint4* bs = (const uint4*)(g_posqh + ((size_t)h * POSJ + j) * HD);
            uint4* bd = (uint4*)(Bandh + tid * 72);
#pragma unroll
            for (int i = 0; i < 8; i++) bd[i] = bs[i];
        }
        __syncthreads();

#pragma unroll
        for (int pass = 0; pass < 2; pass++) {
            float4 t[8];
#pragma unroll
            for (int f = 0; f < 8; f++) t[f] = make_float4(0.f, 0.f, 0.f, 0.f);
#pragma unroll
            for (int c = 0; c < 4; c++) {
                uint32_t a[4];
                const __half* kr = Ksh + qq * 72 + 16 * c + 2 * tg;
                a[0] = *(const uint32_t*)kr;
                a[1] = *(const uint32_t*)(kr + 8 * 72);
                a[2] = *(const uint32_t*)(kr + 8);
                a[3] = *(const uint32_t*)(kr + 8 * 72 + 8);
#pragma unroll
                for (int f = 0; f < 8; f++) {
                    uint32_t bb[2];
                    const __half* pb = Bandh + (64 * pass + 8 * f + g) * 72 + 16 * c + 2 * tg;
                    bb[0] = *(const uint32_t*)pb;
                    bb[1] = *(const uint32_t*)(pb + 8);
                    mma_f16(t[f], a, bb);
                }
            }
#pragma unroll
            for (int f = 0; f < 8; f++) {
                float* p0 = Prod + qq * 132 + 64 * pass + 8 * f + 2 * tg;
                p0[0] = t[f].x; p0[1] = t[f].y;
                p0[8 * 132] = t[f].z; p0[8 * 132 + 1] = t[f].w;
            }
        }
        __syncthreads();

#pragma unroll
        for (int f = 0; f < 8; f++) {
            const int kk = 8 * f + 2 * tg;
            sfr[f].x += Prod[kk * 132 + qq - kk + 63];
            sfr[f].y += Prod[(kk + 1) * 132 + qq - kk + 62];
            sfr[f].z += Prod[kk * 132 + qq - kk + 71];
            sfr[f].w += Prod[(kk + 1) * 132 + qq - kk + 70];
            const float mk0 = Mf[k0 + kk], mk1 = Mf[k0 + kk + 1];
            sfr[f].x = sfr[f].x * SCORE_SCALE + mk0;
            sfr[f].y = sfr[f].y * SCORE_SCALE + mk1;
            sfr[f].z = sfr[f].z * SCORE_SCALE + mk0;
            sfr[f].w = sfr[f].w * SCORE_SCALE + mk1;
        }

        float r0 = -1e30f, r1 = -1e30f;
#pragma unroll
        for (int f = 0; f < 8; f++) {
            r0 = fmaxf(r0, fmaxf(sfr[f].x, sfr[f].y));
            r1 = fmaxf(r1, fmaxf(sfr[f].z, sfr[f].w));
        }
        r0 = fmaxf(r0, __shfl_xor_sync(0xffffffffu, r0, 1));
        r0 = fmaxf(r0, __shfl_xor_sync(0xffffffffu, r0, 2));
        r1 = fmaxf(r1, __shfl_xor_sync(0xffffffffu, r1, 1));
        r1 = fmaxf(r1, __shfl_xor_sync(0xffffffffu, r1, 2));
        const float nm0 = fmaxf(m0, r0), nm1 = fmaxf(m1, r1);
        const float sc0 = __expf(m0 - nm0), sc1 = __expf(m1 - nm1);
        float rs0 = 0.f, rs1 = 0.f;
#pragma unroll
        for (int f = 0; f < 8; f++) {
            const float px = __expf(sfr[f].x - nm0);
            const float py = __expf(sfr[f].y - nm0);
            const float pz = __expf(sfr[f].z - nm1);
            const float pw = __expf(sfr[f].w - nm1);
            rs0 += px + py; rs1 += pz + pw;
            *(__half2*)(Ps + qq * 72 + 8 * f + 2 * tg) = __floats2half2_rn(px, py);
            *(__half2*)(Ps + (qq + 8) * 72 + 8 * f + 2 * tg) = __floats2half2_rn(pz, pw);
            acc[f].x *= sc0; acc[f].y *= sc0;
            acc[f].z *= sc1; acc[f].w *= sc1;
        }
        rs0 += __shfl_xor_sync(0xffffffffu, rs0, 1);
        rs0 += __shfl_xor_sync(0xffffffffu, rs0, 2);
        rs1 += __shfl_xor_sync(0xffffffffu, rs1, 1);
        rs1 += __shfl_xor_sync(0xffffffffu, rs1, 2);
        l0 = l0 * sc0 + rs0;
        l1 = l1 * sc1 + rs1;
        m0 = nm0; m1 = nm1;

        __syncwarp();

#pragma unroll
        for (int c = 0; c < 4; c++) {
            uint32_t a[4];
            const __half* pr = Ps + qq * 72 + 16 * c + 2 * tg;
            a[0] = *(const uint32_t*)pr;
            a[1] = *(const uint32_t*)(pr + 8 * 72);
            a[2] = *(const uint32_t*)(pr + 8);
            a[3] = *(const uint32_t*)(pr + 8 * 72 + 8);
#pragma unroll
            for (int f = 0; f < 8; f++) {
                uint32_t bb[2];
                const __half* vb = Vth + (8 * f + g) * 72 + 16 * c + 2 * tg;
                bb[0] = *(const uint32_t*)vb;
                bb[1] = *(const uint32_t*)(vb + 8);
                mma_f16(acc[f], a, bb);
            }
        }
    }

    const float inv0 = 1.0f / l0, inv1 = 1.0f / l1;
    float* orow0 = out + ((size_t)b * S_LEN + q0 + qq) * DIM + h * HD;
    float* orow1 = orow0 + 8 * DIM;
#pragma unroll
    for (int f = 0; f < 8; f++) {
        const int col = 8 * f + 2 * tg;
        *(float2*)(orow0 + col) = make_float2(acc[f].x * inv0, acc[f].y * inv0);
        *(float2*)(orow1 + col) = make_float2(acc[f].z * inv1, acc[f].w * inv1);
    }
}

// ---------------------------------------------------------------------------
extern "C" void kernel_launch(void* const* d_in, const int* in_sizes, int n_in,
                              void* d_out, int out_size)
{
    const float* x    = (const float*)d_in[0];
    const float* rel  = (const float*)d_in[1];
    const float* mask = (const float*)d_in[2];
    const float* Wq   = (const float*)d_in[3];
    const float* bq   = (const float*)d_in[4];
    const float* Wk   = (const float*)d_in[5];
    const float* bk   = (const float*)d_in[6];
    const float* Wv   = (const float*)d_in[7];
    const float* bv   = (const float*)d_in[8];
    float* out = (float*)d_out;

    // resolve device-global scratch addresses (host side, capture-safe)
    __half *xh, *wqh, *wkh, *wvh, *relh;
    cudaGetSymbolAddress((void**)&xh, g_xh);
    cudaGetSymbolAddress((void**)&wqh, g_wqh);
    cudaGetSymbolAddress((void**)&wkh, g_wkh);
    cudaGetSymbolAddress((void**)&wvh, g_wvh);
    cudaGetSymbolAddress((void**)&relh, g_relh);

    // pre-convert all GEMM operands to fp16
    cvt_f16<<<2048, 256>>>(x, xh, NB * S_LEN * DIM / 8);
    cvt_f16<<<512, 256>>>(Wq, wqh, DIM * DIM / 8);
    cvt_f16<<<512, 256>>>(Wk, wkh, DIM * DIM / 8);
    cvt_f16<<<512, 256>>>(Wv, wvh, DIM * DIM / 8);
    cvt_f16<<<512, 256>>>(rel, relh, POSJ * DIM / 8);

    // fp16 projections: token (Q,K,V) and pos (posQ, posK)
    proj_h<0><<<dim3(8, 32, 3), dim3(128)>>>(xh, wqh, wkh, wvh, bq, bk, bv);
    proj_h<1><<<dim3(8, 8, 2), dim3(128)>>>(relh, wqh, wkh, wkh, bq, bk, bk);

    // fused fp16 attention with in-tile c2p/p2c
    cudaFuncSetAttribute(attn2_kernel, cudaFuncAttributeMaxDynamicSharedMemorySize,
                         ATTN2_SMEM);
    attn2_kernel<<<dim3(8, BH), dim3(128), ATTN2_SMEM>>>(mask, out);
}

// round 14
// speedup vs baseline: 1.2038x; 1.0118x over previous
#include <cuda_runtime.h>
#include <cuda_fp16.h>
#include <math.h>
#include <stdint.h>

#define S_LEN 512
#define HD    64
#define NH    16
#define NB    8
#define BH    128          // NB*NH
#define DIM   1024
#define POSJ  1024
#define SCORE_SCALE 0.07216878364870322f   // 1/sqrt(64*3)
#define QPITCH 40          // proj smem row pitch in halves (conflict-free)
#define NSTAGE (DIM / 32)  // 32 stages of BK=32 cover the full K reduction

// ---------------- scratch (static device globals; no runtime allocation) ----
__device__ __half g_qh[BH * S_LEN * HD];           // [b,h,s,d]
__device__ __half g_kh[BH * S_LEN * HD];
__device__ __half g_vh[BH * S_LEN * HD];
__device__ __half g_posqh[NH * POSJ * HD];         // [h,j,d]
__device__ __half g_poskh[NH * POSJ * HD];
// pre-converted fp16 inputs
__device__ __half g_xh[NB * S_LEN * DIM];
__device__ __half g_wqh[DIM * DIM];
__device__ __half g_wkh[DIM * DIM];
__device__ __half g_wvh[DIM * DIM];
__device__ __half g_relh[POSJ * DIM];

// ---------------------------------------------------------------------------
// helpers
// ---------------------------------------------------------------------------
__device__ __forceinline__ void mma_f16(float4& c, const uint32_t* a, const uint32_t* b) {
    asm volatile(
        "mma.sync.aligned.m16n8k16.row.col.f32.f16.f16.f32 "
        "{%0,%1,%2,%3}, {%4,%5,%6,%7}, {%8,%9}, {%0,%1,%2,%3};\n"
        : "+f"(c.x), "+f"(c.y), "+f"(c.z), "+f"(c.w)
        : "r"(a[0]), "r"(a[1]), "r"(a[2]), "r"(a[3]), "r"(b[0]), "r"(b[1]));
}
__device__ __forceinline__ uint32_t p2(float a, float b) {
    __half2 h = __floats2half2_rn(a, b);
    return *(uint32_t*)&h;
}
__device__ __forceinline__ void cpa16(uint32_t dst, const void* src) {
    asm volatile("cp.async.ca.shared.global [%0], [%1], 16;" :: "r"(dst), "l"(src) : "memory");
}

// ---------------------------------------------------------------------------
// f32 -> f16 bulk convert (8 floats / thread)
// ---------------------------------------------------------------------------
__global__ void __launch_bounds__(256) cvt_f16(const float* __restrict__ src,
                                               __half* __restrict__ dst, int n8)
{
    const int i = blockIdx.x * blockDim.x + threadIdx.x;
    if (i < n8) {
        const float4 f0 = ((const float4*)src)[2 * i];
        const float4 f1 = ((const float4*)src)[2 * i + 1];
        uint4 u;
        u.x = p2(f0.x, f0.y); u.y = p2(f0.z, f0.w);
        u.z = p2(f1.x, f1.y); u.w = p2(f1.z, f1.w);
        ((uint4*)dst)[i] = u;
    }
}

// ---------------------------------------------------------------------------
// fp16 projection GEMM (fp16 inputs): C = A * W^T + bias -> __half out
// Block 128x128, BK=32 x 32 stages (full K=1024), 128 threads = 4 warps
// (2m x 2n), warp tile 64x64. cp.async double-buffered staging.
// ---------------------------------------------------------------------------
template <int MODE>
__global__ void __launch_bounds__(128) proj_h(const __half* __restrict__ A,
                                              const __half* __restrict__ W0,
                                              const __half* __restrict__ W1,
                                              const __half* __restrict__ W2,
                                              const float* __restrict__ bias0,
                                              const float* __restrict__ bias1,
                                              const float* __restrict__ bias2)
{
    const int z = blockIdx.z;
    const __half* W   = (z == 0) ? W0 : (z == 1) ? W1 : W2;
    const float* bias = (z == 0) ? bias0 : (z == 1) ? bias1 : bias2;
    __half* out = (MODE == 0) ? ((z == 0) ? g_qh : (z == 1) ? g_kh : g_vh)
                              : ((z == 0) ? g_posqh : g_poskh);

    __shared__ __half As[2][128 * QPITCH];
    __shared__ __half Bs[2][128 * QPITCH];

    const int tid  = threadIdx.x;
    const int warp = tid >> 5, lane = tid & 31;
    const int wm = warp >> 1, wn = warp & 1;
    const int g  = lane >> 2, tg = lane & 3;
    const int bm = blockIdx.y, bn = blockIdx.x;

    const __half* Ap = A + (size_t)(bm * 128 + tid) * DIM;
    const __half* Wp = W + (size_t)(bn * 128 + tid) * DIM;
    const uint32_t a0 = (uint32_t)__cvta_generic_to_shared(&As[0][tid * QPITCH]);
    const uint32_t b0 = (uint32_t)__cvta_generic_to_shared(&Bs[0][tid * QPITCH]);
    const uint32_t stage_bytes = 128 * QPITCH * 2;

    float4 c[4][8];
#pragma unroll
    for (int t = 0; t < 4; t++)
#pragma unroll
        for (int f = 0; f < 8; f++) c[t][f] = make_float4(0.f, 0.f, 0.f, 0.f);

    {
#pragma unroll
        for (int ch = 0; ch < 4; ch++) {
            cpa16(a0 + ch * 16, Ap + ch * 8);
            cpa16(b0 + ch * 16, Wp + ch * 8);
        }
        asm volatile("cp.async.commit_group;" ::: "memory");
    }

    for (int s = 0; s < NSTAGE; s++) {
        const int p = s & 1;
        if (s < NSTAGE - 1) {
            const uint32_t ao = a0 + (uint32_t)((s + 1) & 1) * stage_bytes;
            const uint32_t bo = b0 + (uint32_t)((s + 1) & 1) * stage_bytes;
            const __half* as = Ap + (s + 1) * 32;
            const __half* ws = Wp + (s + 1) * 32;
#pragma unroll
            for (int ch = 0; ch < 4; ch++) {
                cpa16(ao + ch * 16, as + ch * 8);
                cpa16(bo + ch * 16, ws + ch * 8);
            }
            asm volatile("cp.async.commit_group;" ::: "memory");
            asm volatile("cp.async.wait_group 1;" ::: "memory");
        } else {
            asm volatile("cp.async.wait_group 0;" ::: "memory");
        }
        __syncthreads();

#pragma unroll
        for (int k16 = 0; k16 < 2; k16++) {
            const int kb = k16 * 16 + 2 * tg;
            uint32_t a[4][4], b[8][2];
#pragma unroll
            for (int t = 0; t < 4; t++) {
                const __half* ar = &As[p][(wm * 64 + t * 16 + g) * QPITCH + kb];
                a[t][0] = *(const uint32_t*)ar;
                a[t][1] = *(const uint32_t*)(ar + 8 * QPITCH);
                a[t][2] = *(const uint32_t*)(ar + 8);
                a[t][3] = *(const uint32_t*)(ar + 8 * QPITCH + 8);
            }
#pragma unroll
            for (int f = 0; f < 8; f++) {
                const __half* br = &Bs[p][(wn * 64 + f * 8 + g) * QPITCH + kb];
                b[f][0] = *(const uint32_t*)br;
                b[f][1] = *(const uint32_t*)(br + 8);
            }
#pragma unroll
            for (int t = 0; t < 4; t++)
#pragma unroll
                for (int f = 0; f < 8; f++)
                    mma_f16(c[t][f], a[t], b[f]);
        }
        __syncthreads();
    }

#pragma unroll
    for (int t = 0; t < 4; t++) {
        const int row0 = bm * 128 + wm * 64 + t * 16 + g;
#pragma unroll
        for (int f = 0; f < 8; f++) {
            const int col = bn * 128 + wn * 64 + f * 8 + 2 * tg;
            const float bb0 = bias[col], bb1 = bias[col + 1];
            __half2 h0 = __floats2half2_rn(c[t][f].x + bb0, c[t][f].y + bb1);
            __half2 h1 = __floats2half2_rn(c[t][f].z + bb0, c[t][f].w + bb1);
            const int h = col >> 6, d = col & 63;
            if (MODE == 0) {
                const int bi0 = row0 >> 9, s0 = row0 & 511;
                *(__half2*)(out + ((size_t)(bi0 * NH + h) * S_LEN + s0) * HD + d) = h0;
                const int r1 = row0 + 8;
                const int bi1 = r1 >> 9, s1 = r1 & 511;
                *(__half2*)(out + ((size_t)(bi1 * NH + h) * S_LEN + s1) * HD + d) = h1;
            } else {
                *(__half2*)(out + ((size_t)h * POSJ + row0) * HD + d) = h0;
                *(__half2*)(out + ((size_t)h * POSJ + row0 + 8) * HD + d) = h1;
            }
        }
    }
}

// ---------------------------------------------------------------------------
// Fused fp16 attention; band GEMMs predicated to the gathered diagonal band.
// C2P keep: tile cols ∩ [16w, 16w+78]; P2C keep: tile cols ∩ [48-16w, 126-16w].
// ---------------------------------------------------------------------------
#define SM_QH    0
#define SM_KSH   9216
#define SM_VTH   18432
#define SM_BAND  27648
#define SM_PROD  46080
#define SM_PS    79872
#define SM_MASK  89088
#define ATTN2_SMEM (89088 + 2048)

__global__ void __launch_bounds__(128) attn2_kernel(const float* __restrict__ mask,
                                                    float* __restrict__ out)
{
    extern __shared__ char smraw[];
    __half* Qh   = (__half*)(smraw + SM_QH);     // [64][72]
    __half* Ksh  = (__half*)(smraw + SM_KSH);    // [64][72]
    __half* Vth  = (__half*)(smraw + SM_VTH);    // [64][72] (V transposed)
    __half* Bandh= (__half*)(smraw + SM_BAND);   // [128][72]
    float*  Prod = (float*)(smraw + SM_PROD);    // [64][132]
    __half* Ps   = (__half*)(smraw + SM_PS);     // [64][72]
    float*  Mf   = (float*)(smraw + SM_MASK);    // [512]

    const int tid = threadIdx.x;
    const int w = tid >> 5, lane = tid & 31;
    const int g = lane >> 2, tg = lane & 3;
    const int bh = blockIdx.y;
    const int b = bh >> 4, h = bh & 15;
    const int q0 = blockIdx.x << 6;
    const int wlo = 16 * w;

    {
        const int row = tid >> 1, seg = tid & 1;
        const uint4* src = (const uint4*)(g_qh + ((size_t)bh * S_LEN + q0 + row) * HD + seg * 32);
        uint4* dst = (uint4*)(Qh + row * 72 + seg * 32);
#pragma unroll
        for (int i = 0; i < 4; i++) dst[i] = src[i];
        *(float4*)(Mf + tid * 4) = *(const float4*)(mask + b * S_LEN + tid * 4);
    }

    const int qq = 16 * w + g;

    float4 sfr[8], acc[8];
    float m0 = -1e30f, m1 = -1e30f, l0 = 0.f, l1 = 0.f;
#pragma unroll
    for (int f = 0; f < 8; f++) acc[f] = make_float4(0.f, 0.f, 0.f, 0.f);

    for (int kt = 0; kt < 8; kt++) {
        const int k0 = kt << 6;
        __syncthreads();

        {
            const int row = tid >> 1, seg = tid & 1;
            const uint4* ks = (const uint4*)(g_kh + ((size_t)bh * S_LEN + k0 + row) * HD + seg * 32);
            uint4* kd = (uint4*)(Ksh + row * 72 + seg * 32);
#pragma unroll
            for (int i = 0; i < 4; i++) kd[i] = ks[i];

            const __half2* vs = (const __half2*)(g_vh + ((size_t)bh * S_LEN + k0 + row) * HD + seg * 32);
#pragma unroll
            for (int i = 0; i < 16; i++) {
                __half2 v = vs[i];
                const int d = seg * 32 + 2 * i;
                Vth[d * 72 + row] = __low2half(v);
                Vth[(d + 1) * 72 + row] = __high2half(v);
            }
            int j = q0 - k0 + 449 + tid;
            j = j < 0 ? 0 : (j > 1023 ? 1023 : j);
            const uint4* bs = (const uint4*)(g_poskh + ((size_t)h * POSJ + j) * HD);
            uint4* bd = (uint4*)(Bandh + tid * 72);
#pragma unroll
            for (int i = 0; i < 8; i++) bd[i] = bs[i];
        }
        __syncthreads();

        // ---- S = Q K^T ------------------------------------------------------
#pragma unroll
        for (int f = 0; f < 8; f++) sfr[f] = make_float4(0.f, 0.f, 0.f, 0.f);
#pragma unroll
        for (int c = 0; c < 4; c++) {
            uint32_t a[4];
            const __half* qr = Qh + qq * 72 + 16 * c + 2 * tg;
            a[0] = *(const uint32_t*)qr;
            a[1] = *(const uint32_t*)(qr + 8 * 72);
            a[2] = *(const uint32_t*)(qr + 8);
            a[3] = *(const uint32_t*)(qr + 8 * 72 + 8);
#pragma unroll
            for (int f = 0; f < 8; f++) {
                uint32_t bb[2];
                const __half* kb = Ksh + (8 * f + g) * 72 + 16 * c + 2 * tg;
                bb[0] = *(const uint32_t*)kb;
                bb[1] = *(const uint32_t*)(kb + 8);
                mma_f16(sfr[f], a, bb);
            }
        }

        // ---- C2P band GEMM (predicated to cols [16w, 16w+78]) --------------
#pragma unroll
        for (int pass = 0; pass < 2; pass++) {
            float4 t[8];
#pragma unroll
            for (int f = 0; f < 8; f++) t[f] = make_float4(0.f, 0.f, 0.f, 0.f);
#pragma unroll
            for (int c = 0; c < 4; c++) {
                uint32_t a[4];
                const __half* qr = Qh + qq * 72 + 16 * c + 2 * tg;
                a[0] = *(const uint32_t*)qr;
                a[1] = *(const uint32_t*)(qr + 8 * 72);
                a[2] = *(const uint32_t*)(qr + 8);
                a[3] = *(const uint32_t*)(qr + 8 * 72 + 8);
#pragma unroll
                for (int f = 0; f < 8; f++) {
                    const int cb = 64 * pass + 8 * f;
                    if (cb + 7 >= wlo && cb <= wlo + 78) {
                        uint32_t bb[2];
                        const __half* pb = Bandh + (cb + g) * 72 + 16 * c + 2 * tg;
                        bb[0] = *(const uint32_t*)pb;
                        bb[1] = *(const uint32_t*)(pb + 8);
                        mma_f16(t[f], a, bb);
                    }
                }
            }
#pragma unroll
            for (int f = 0; f < 8; f++) {
                const int cb = 64 * pass + 8 * f;
                if (cb + 7 >= wlo && cb <= wlo + 78) {
                    float* p0 = Prod + qq * 132 + cb + 2 * tg;
                    p0[0] = t[f].x; p0[1] = t[f].y;
                    p0[8 * 132] = t[f].z; p0[8 * 132 + 1] = t[f].w;
                }
            }
        }
        __syncthreads();

        // ---- gather c2p (Prod[q][q-k+63]); load posQ band -------------------
#pragma unroll
        for (int f = 0; f < 8; f++) {
            const int kk = 8 * f + 2 * tg;
            sfr[f].x += Prod[qq * 132 + qq - kk + 63];
            sfr[f].y += Prod[qq * 132 + qq - kk + 62];
            sfr[f].z += Prod[(qq + 8) * 132 + qq - kk + 71];
            sfr[f].w += Prod[(qq + 8) * 132 + qq - kk + 70];
        }
        {
            int j = q0 - k0 + 449 + tid;
            j = j < 0 ? 0 : (j > 1023 ? 1023 : j);
            const uint4* bs = (const uint4*)(g_posqh + ((size_t)h * POSJ + j) * HD);
            uint4* bd = (uint4*)(Bandh + tid * 72);
#pragma unroll
            for (int i = 0; i < 8; i++) bd[i] = bs[i];
        }
        __syncthreads();

        // ---- P2C band GEMM (predicated to cols [48-16w, 126-16w]) ----------
#pragma unroll
        for (int pass = 0; pass < 2; pass++) {
            float4 t[8];
#pragma unroll
            for (int f = 0; f < 8; f++) t[f] = make_float4(0.f, 0.f, 0.f, 0.f);
#pragma unroll
            for (int c = 0; c < 4; c++) {
                uint32_t a[4];
                const __half* kr = Ksh + qq * 72 + 16 * c + 2 * tg;
                a[0] = *(const uint32_t*)kr;
                a[1] = *(const uint32_t*)(kr + 8 * 72);
                a[2] = *(const uint32_t*)(kr + 8);
                a[3] = *(const uint32_t*)(kr + 8 * 72 + 8);
#pragma unroll
                for (int f = 0; f < 8; f++) {
                    const int cb = 64 * pass + 8 * f;
                    if (cb + 7 >= 48 - wlo && cb <= 126 - wlo) {
                        uint32_t bb[2];
                        const __half* pb = Bandh + (cb + g) * 72 + 16 * c + 2 * tg;
                        bb[0] = *(const uint32_t*)pb;
                        bb[1] = *(const uint32_t*)(pb + 8);
                        mma_f16(t[f], a, bb);
                    }
                }
            }
#pragma unroll
            for (int f = 0; f < 8; f++) {
                const int cb = 64 * pass + 8 * f;
                if (cb + 7 >= 48 - wlo && cb <= 126 - wlo) {
                    float* p0 = Prod + qq * 132 + cb + 2 * tg;
                    p0[0] = t[f].x; p0[1] = t[f].y;
                    p0[8 * 132] = t[f].z; p0[8 * 132 + 1] = t[f].w;
                }
            }
        }
        __syncthreads();

        // ---- gather p2c (Prod[k][q-k+63]), scale + mask ---------------------
#pragma unroll
        for (int f = 0; f < 8; f++) {
            const int kk = 8 * f + 2 * tg;
            sfr[f].x += Prod[kk * 132 + qq - kk + 63];
            sfr[f].y += Prod[(kk + 1) * 132 + qq - kk + 62];
            sfr[f].z += Prod[kk * 132 + qq - kk + 71];
            sfr[f].w += Prod[(kk + 1) * 132 + qq - kk + 70];
            const float mk0 = Mf[k0 + kk], mk1 = Mf[k0 + kk + 1];
            sfr[f].x = sfr[f].x * SCORE_SCALE + mk0;
            sfr[f].y = sfr[f].y * SCORE_SCALE + mk1;
            sfr[f].z = sfr[f].z * SCORE_SCALE + mk0;
            sfr[f].w = sfr[f].w * SCORE_SCALE + mk1;
        }

        // ---- online softmax -------------------------------------------------
        float r0 = -1e30f, r1 = -1e30f;
#pragma unroll
        for (int f = 0; f < 8; f++) {
            r0 = fmaxf(r0, fmaxf(sfr[f].x, sfr[f].y));
            r1 = fmaxf(r1, fmaxf(sfr[f].z, sfr[f].w));
        }
        r0 = fmaxf(r0, __shfl_xor_sync(0xffffffffu, r0, 1));
        r0 = fmaxf(r0, __shfl_xor_sync(0xffffffffu, r0, 2));
        r1 = fmaxf(r1, __shfl_xor_sync(0xffffffffu, r1, 1));
        r1 = fmaxf(r1, __shfl_xor_sync(0xffffffffu, r1, 2));
        const float nm0 = fmaxf(m0, r0), nm1 = fmaxf(m1, r1);
        const float sc0 = __expf(m0 - nm0), sc1 = __expf(m1 - nm1);
        float rs0 = 0.f, rs1 = 0.f;
#pragma unroll
        for (int f = 0; f < 8; f++) {
            const float px = __expf(sfr[f].x - nm0);
            const float py = __expf(sfr[f].y - nm0);
            const float pz = __expf(sfr[f].z - nm1);
            const float pw = __expf(sfr[f].w - nm1);
            rs0 += px + py; rs1 += pz + pw;
            *(__half2*)(Ps + qq * 72 + 8 * f + 2 * tg) = __floats2half2_rn(px, py);
            *(__half2*)(Ps + (qq + 8) * 72 + 8 * f + 2 * tg) = __floats2half2_rn(pz, pw);
            acc[f].x *= sc0; acc[f].y *= sc0;
            acc[f].z *= sc1; acc[f].w *= sc1;
        }
        rs0 += __shfl_xor_sync(0xffffffffu, rs0, 1);
        rs0 += __shfl_xor_sync(0xffffffffu, rs0, 2);
        rs1 += __shfl_xor_sync(0xffffffffu, rs1, 1);
        rs1 += __shfl_xor_sync(0xffffffffu, rs1, 2);
        l0 = l0 * sc0 + rs0;
        l1 = l1 * sc1 + rs1;
        m0 = nm0; m1 = nm1;

        __syncwarp();

        // ---- PV: acc += P @ V ----------------------------------------------
#pragma unroll
        for (int c = 0; c < 4; c++) {
            uint32_t a[4];
            const __half* pr = Ps + qq * 72 + 16 * c + 2 * tg;
            a[0] = *(const uint32_t*)pr;
            a[1] = *(const uint32_t*)(pr + 8 * 72);
            a[2] = *(const uint32_t*)(pr + 8);
            a[3] = *(const uint32_t*)(pr + 8 * 72 + 8);
#pragma unroll
            for (int f = 0; f < 8; f++) {
                uint32_t bb[2];
                const __half* vb = Vth + (8 * f + g) * 72 + 16 * c + 2 * tg;
                bb[0] = *(const uint32_t*)vb;
                bb[1] = *(const uint32_t*)(vb + 8);
                mma_f16(acc[f], a, bb);
            }
        }
    }

    const float inv0 = 1.0f / l0, inv1 = 1.0f / l1;
    float* orow0 = out + ((size_t)b * S_LEN + q0 + qq) * DIM + h * HD;
    float* orow1 = orow0 + 8 * DIM;
#pragma unroll
    for (int f = 0; f < 8; f++) {
        const int col = 8 * f + 2 * tg;
        *(float2*)(orow0 + col) = make_float2(acc[f].x * inv0, acc[f].y * inv0);
        *(float2*)(orow1 + col) = make_float2(acc[f].z * inv1, acc[f].w * inv1);
    }
}

// ---------------------------------------------------------------------------
extern "C" void kernel_launch(void* const* d_in, const int* in_sizes, int n_in,
                              void* d_out, int out_size)
{
    const float* x    = (const float*)d_in[0];
    const float* rel  = (const float*)d_in[1];
    const float* mask = (const float*)d_in[2];
    const float* Wq   = (const float*)d_in[3];
    const float* bq   = (const float*)d_in[4];
    const float* Wk   = (const float*)d_in[5];
    const float* bk   = (const float*)d_in[6];
    const float* Wv   = (const float*)d_in[7];
    const float* bv   = (const float*)d_in[8];
    float* out = (float*)d_out;

    __half *xh, *wqh, *wkh, *wvh, *relh;
    cudaGetSymbolAddress((void**)&xh, g_xh);
    cudaGetSymbolAddress((void**)&wqh, g_wqh);
    cudaGetSymbolAddress((void**)&wkh, g_wkh);
    cudaGetSymbolAddress((void**)&wvh, g_wvh);
    cudaGetSymbolAddress((void**)&relh, g_relh);

    // pre-convert all GEMM operands to fp16
    cvt_f16<<<2048, 256>>>(x, xh, NB * S_LEN * DIM / 8);
    cvt_f16<<<512, 256>>>(Wq, wqh, DIM * DIM / 8);
    cvt_f16<<<512, 256>>>(Wk, wkh, DIM * DIM / 8);
    cvt_f16<<<512, 256>>>(Wv, wvh, DIM * DIM / 8);
    cvt_f16<<<512, 256>>>(rel, relh, POSJ * DIM / 8);

    // fp16 projections: token (Q,K,V) and pos (posQ, posK)
    proj_h<0><<<dim3(8, 32, 3), dim3(128)>>>(xh, wqh, wkh, wvh, bq, bk, bv);
    proj_h<1><<<dim3(8, 8, 2), dim3(128)>>>(relh, wqh, wkh, wkh, bq, bk, bk);

    // fused fp16 attention with predicated in-tile c2p/p2c
    cudaFuncSetAttribute(attn2_kernel, cudaFuncAttributeMaxDynamicSharedMemorySize,
                         ATTN2_SMEM);
    attn2_kernel<<<dim3(8, BH), dim3(128), ATTN2_SMEM>>>(mask, out);
}

// round 15
// speedup vs baseline: 1.2349x; 1.0259x over previous
#include <cuda_runtime.h>
#include <cuda_fp16.h>
#include <math.h>
#include <stdint.h>

#define S_LEN 512
#define HD    64
#define NH    16
#define NB    8
#define BH    128          // NB*NH
#define DIM   1024
#define POSJ  1024
#define SCORE_SCALE 0.07216878364870322f   // 1/sqrt(64*3)
#define QPITCH 40          // proj smem row pitch in halves (conflict-free)
#define NSTAGE (DIM / 32)  // 32 stages of BK=32 cover the full K reduction

// ---------------- scratch (static device globals; no runtime allocation) ----
__device__ __half g_qh[BH * S_LEN * HD];           // [b,h,s,d]
__device__ __half g_kh[BH * S_LEN * HD];
__device__ __half g_vh[BH * S_LEN * HD];
__device__ __half g_posqh[NH * POSJ * HD];         // [h,j,d]
__device__ __half g_poskh[NH * POSJ * HD];
// pre-converted fp16 inputs
__device__ __half g_xh[NB * S_LEN * DIM];
__device__ __half g_wqh[DIM * DIM];
__device__ __half g_wkh[DIM * DIM];
__device__ __half g_wvh[DIM * DIM];
__device__ __half g_relh[POSJ * DIM];

// ---------------------------------------------------------------------------
// helpers
// ---------------------------------------------------------------------------
__device__ __forceinline__ void mma_f16(float4& c, const uint32_t* a, const uint32_t* b) {
    asm volatile(
        "mma.sync.aligned.m16n8k16.row.col.f32.f16.f16.f32 "
        "{%0,%1,%2,%3}, {%4,%5,%6,%7}, {%8,%9}, {%0,%1,%2,%3};\n"
        : "+f"(c.x), "+f"(c.y), "+f"(c.z), "+f"(c.w)
        : "r"(a[0]), "r"(a[1]), "r"(a[2]), "r"(a[3]), "r"(b[0]), "r"(b[1]));
}
__device__ __forceinline__ uint32_t p2(float a, float b) {
    __half2 h = __floats2half2_rn(a, b);
    return *(uint32_t*)&h;
}
__device__ __forceinline__ void cpa16(uint32_t dst, const void* src) {
    asm volatile("cp.async.ca.shared.global [%0], [%1], 16;" :: "r"(dst), "l"(src) : "memory");
}

// ---------------------------------------------------------------------------
// f32 -> f16 bulk convert (8 floats / thread)
// ---------------------------------------------------------------------------
__global__ void __launch_bounds__(256) cvt_f16(const float* __restrict__ src,
                                               __half* __restrict__ dst, int n8)
{
    const int i = blockIdx.x * blockDim.x + threadIdx.x;
    if (i < n8) {
        const float4 f0 = ((const float4*)src)[2 * i];
        const float4 f1 = ((const float4*)src)[2 * i + 1];
        uint4 u;
        u.x = p2(f0.x, f0.y); u.y = p2(f0.z, f0.w);
        u.z = p2(f1.x, f1.y); u.w = p2(f1.z, f1.w);
        ((uint4*)dst)[i] = u;
    }
}

// ---------------------------------------------------------------------------
// fp16 projection GEMM (fp16 inputs): C = A * W^T + bias -> __half out
// Block 128x128, BK=32 x 32 stages (full K=1024), 128 threads = 4 warps
// (2m x 2n), warp tile 64x64. cp.async double-buffered staging.
// ---------------------------------------------------------------------------
template <int MODE>
__global__ void __launch_bounds__(128) proj_h(const __half* __restrict__ A,
                                              const __half* __restrict__ W0,
                                              const __half* __restrict__ W1,
                                              const __half* __restrict__ W2,
                                              const float* __restrict__ bias0,
                                              const float* __restrict__ bias1,
                                              const float* __restrict__ bias2)
{
    const int z = blockIdx.z;
    const __half* W   = (z == 0) ? W0 : (z == 1) ? W1 : W2;
    const float* bias = (z == 0) ? bias0 : (z == 1) ? bias1 : bias2;
    __half* out = (MODE == 0) ? ((z == 0) ? g_qh : (z == 1) ? g_kh : g_vh)
                              : ((z == 0) ? g_posqh : g_poskh);

    __shared__ __half As[2][128 * QPITCH];
    __shared__ __half Bs[2][128 * QPITCH];

    const int tid  = threadIdx.x;
    const int warp = tid >> 5, lane = tid & 31;
    const int wm = warp >> 1, wn = warp & 1;
    const int g  = lane >> 2, tg = lane & 3;
    const int bm = blockIdx.y, bn = blockIdx.x;

    const __half* Ap = A + (size_t)(bm * 128 + tid) * DIM;
    const __half* Wp = W + (size_t)(bn * 128 + tid) * DIM;
    const uint32_t a0 = (uint32_t)__cvta_generic_to_shared(&As[0][tid * QPITCH]);
    const uint32_t b0 = (uint32_t)__cvta_generic_to_shared(&Bs[0][tid * QPITCH]);
    const uint32_t stage_bytes = 128 * QPITCH * 2;

    float4 c[4][8];
#pragma unroll
    for (int t = 0; t < 4; t++)
#pragma unroll
        for (int f = 0; f < 8; f++) c[t][f] = make_float4(0.f, 0.f, 0.f, 0.f);

    {
#pragma unroll
        for (int ch = 0; ch < 4; ch++) {
            cpa16(a0 + ch * 16, Ap + ch * 8);
            cpa16(b0 + ch * 16, Wp + ch * 8);
        }
        asm volatile("cp.async.commit_group;" ::: "memory");
    }

    for (int s = 0; s < NSTAGE; s++) {
        const int p = s & 1;
        if (s < NSTAGE - 1) {
            const uint32_t ao = a0 + (uint32_t)((s + 1) & 1) * stage_bytes;
            const uint32_t bo = b0 + (uint32_t)((s + 1) & 1) * stage_bytes;
            const __half* as = Ap + (s + 1) * 32;
            const __half* ws = Wp + (s + 1) * 32;
#pragma unroll
            for (int ch = 0; ch < 4; ch++) {
                cpa16(ao + ch * 16, as + ch * 8);
                cpa16(bo + ch * 16, ws + ch * 8);
            }
            asm volatile("cp.async.commit_group;" ::: "memory");
            asm volatile("cp.async.wait_group 1;" ::: "memory");
        } else {
            asm volatile("cp.async.wait_group 0;" ::: "memory");
        }
        __syncthreads();

#pragma unroll
        for (int k16 = 0; k16 < 2; k16++) {
            const int kb = k16 * 16 + 2 * tg;
            uint32_t a[4][4], b[8][2];
#pragma unroll
            for (int t = 0; t < 4; t++) {
                const __half* ar = &As[p][(wm * 64 + t * 16 + g) * QPITCH + kb];
                a[t][0] = *(const uint32_t*)ar;
                a[t][1] = *(const uint32_t*)(ar + 8 * QPITCH);
                a[t][2] = *(const uint32_t*)(ar + 8);
                a[t][3] = *(const uint32_t*)(ar + 8 * QPITCH + 8);
            }
#pragma unroll
            for (int f = 0; f < 8; f++) {
                const __half* br = &Bs[p][(wn * 64 + f * 8 + g) * QPITCH + kb];
                b[f][0] = *(const uint32_t*)br;
                b[f][1] = *(const uint32_t*)(br + 8);
            }
#pragma unroll
            for (int t = 0; t < 4; t++)
#pragma unroll
                for (int f = 0; f < 8; f++)
                    mma_f16(c[t][f], a[t], b[f]);
        }
        __syncthreads();
    }

#pragma unroll
    for (int t = 0; t < 4; t++) {
        const int row0 = bm * 128 + wm * 64 + t * 16 + g;
#pragma unroll
        for (int f = 0; f < 8; f++) {
            const int col = bn * 128 + wn * 64 + f * 8 + 2 * tg;
            const float bb0 = bias[col], bb1 = bias[col + 1];
            __half2 h0 = __floats2half2_rn(c[t][f].x + bb0, c[t][f].y + bb1);
            __half2 h1 = __floats2half2_rn(c[t][f].z + bb0, c[t][f].w + bb1);
            const int h = col >> 6, d = col & 63;
            if (MODE == 0) {
                const int bi0 = row0 >> 9, s0 = row0 & 511;
                *(__half2*)(out + ((size_t)(bi0 * NH + h) * S_LEN + s0) * HD + d) = h0;
                const int r1 = row0 + 8;
                const int bi1 = r1 >> 9, s1 = r1 & 511;
                *(__half2*)(out + ((size_t)(bi1 * NH + h) * S_LEN + s1) * HD + d) = h1;
            } else {
                *(__half2*)(out + ((size_t)h * POSJ + row0) * HD + d) = h0;
                *(__half2*)(out + ((size_t)h * POSJ + row0 + 8) * HD + d) = h1;
            }
        }
    }
}

// ---------------------------------------------------------------------------
// Fused fp16 attention; predicated band GEMMs; Prod stored as fp16 so the
// CTA fits in 74,240 B smem -> 3 CTAs/SM (12 warps, +50% occupancy).
// ---------------------------------------------------------------------------
#define SM_QH    0
#define SM_KSH   9216
#define SM_VTH   18432
#define SM_BAND  27648
#define SM_PROD  46080          // __half [64][132] = 16896 B
#define SM_PS    62976
#define SM_MASK  72192
#define ATTN2_SMEM (72192 + 2048)

__global__ void __launch_bounds__(128, 3) attn2_kernel(const float* __restrict__ mask,
                                                       float* __restrict__ out)
{
    extern __shared__ char smraw[];
    __half* Qh   = (__half*)(smraw + SM_QH);     // [64][72]
    __half* Ksh  = (__half*)(smraw + SM_KSH);    // [64][72]
    __half* Vth  = (__half*)(smraw + SM_VTH);    // [64][72] (V transposed)
    __half* Bandh= (__half*)(smraw + SM_BAND);   // [128][72]
    __half* ProdH= (__half*)(smraw + SM_PROD);   // [64][132] fp16
    __half* Ps   = (__half*)(smraw + SM_PS);     // [64][72]
    float*  Mf   = (float*)(smraw + SM_MASK);    // [512]

    const int tid = threadIdx.x;
    const int w = tid >> 5, lane = tid & 31;
    const int g = lane >> 2, tg = lane & 3;
    const int bh = blockIdx.y;
    const int b = bh >> 4, h = bh & 15;
    const int q0 = blockIdx.x << 6;
    const int wlo = 16 * w;

    {
        const int row = tid >> 1, seg = tid & 1;
        const uint4* src = (const uint4*)(g_qh + ((size_t)bh * S_LEN + q0 + row) * HD + seg * 32);
        uint4* dst = (uint4*)(Qh + row * 72 + seg * 32);
#pragma unroll
        for (int i = 0; i < 4; i++) dst[i] = src[i];
        *(float4*)(Mf + tid * 4) = *(const float4*)(mask + b * S_LEN + tid * 4);
    }

    const int qq = 16 * w + g;

    float4 sfr[8], acc[8];
    float m0 = -1e30f, m1 = -1e30f, l0 = 0.f, l1 = 0.f;
#pragma unroll
    for (int f = 0; f < 8; f++) acc[f] = make_float4(0.f, 0.f, 0.f, 0.f);

    for (int kt = 0; kt < 8; kt++) {
        const int k0 = kt << 6;
        __syncthreads();

        {
            const int row = tid >> 1, seg = tid & 1;
            const uint4* ks = (const uint4*)(g_kh + ((size_t)bh * S_LEN + k0 + row) * HD + seg * 32);
            uint4* kd = (uint4*)(Ksh + row * 72 + seg * 32);
#pragma unroll
            for (int i = 0; i < 4; i++) kd[i] = ks[i];

            const __half2* vs = (const __half2*)(g_vh + ((size_t)bh * S_LEN + k0 + row) * HD + seg * 32);
#pragma unroll
            for (int i = 0; i < 16; i++) {
                __half2 v = vs[i];
                const int d = seg * 32 + 2 * i;
                Vth[d * 72 + row] = __low2half(v);
                Vth[(d + 1) * 72 + row] = __high2half(v);
            }
            int j = q0 - k0 + 449 + tid;
            j = j < 0 ? 0 : (j > 1023 ? 1023 : j);
            const uint4* bs = (const uint4*)(g_poskh + ((size_t)h * POSJ + j) * HD);
            uint4* bd = (uint4*)(Bandh + tid * 72);
#pragma unroll
            for (int i = 0; i < 8; i++) bd[i] = bs[i];
        }
        __syncthreads();

        // ---- S = Q K^T ------------------------------------------------------
#pragma unroll
        for (int f = 0; f < 8; f++) sfr[f] = make_float4(0.f, 0.f, 0.f, 0.f);
#pragma unroll
        for (int c = 0; c < 4; c++) {
            uint32_t a[4];
            const __half* qr = Qh + qq * 72 + 16 * c + 2 * tg;
            a[0] = *(const uint32_t*)qr;
            a[1] = *(const uint32_t*)(qr + 8 * 72);
            a[2] = *(const uint32_t*)(qr + 8);
            a[3] = *(const uint32_t*)(qr + 8 * 72 + 8);
#pragma unroll
            for (int f = 0; f < 8; f++) {
                uint32_t bb[2];
                const __half* kb = Ksh + (8 * f + g) * 72 + 16 * c + 2 * tg;
                bb[0] = *(const uint32_t*)kb;
                bb[1] = *(const uint32_t*)(kb + 8);
                mma_f16(sfr[f], a, bb);
            }
        }

        // ---- C2P band GEMM (predicated to cols [16w, 16w+78]) --------------
#pragma unroll
        for (int pass = 0; pass < 2; pass++) {
            float4 t[8];
#pragma unroll
            for (int f = 0; f < 8; f++) t[f] = make_float4(0.f, 0.f, 0.f, 0.f);
#pragma unroll
            for (int c = 0; c < 4; c++) {
                uint32_t a[4];
                const __half* qr = Qh + qq * 72 + 16 * c + 2 * tg;
                a[0] = *(const uint32_t*)qr;
                a[1] = *(const uint32_t*)(qr + 8 * 72);
                a[2] = *(const uint32_t*)(qr + 8);
                a[3] = *(const uint32_t*)(qr + 8 * 72 + 8);
#pragma unroll
                for (int f = 0; f < 8; f++) {
                    const int cb = 64 * pass + 8 * f;
                    if (cb + 7 >= wlo && cb <= wlo + 78) {
                        uint32_t bb[2];
                        const __half* pb = Bandh + (cb + g) * 72 + 16 * c + 2 * tg;
                        bb[0] = *(const uint32_t*)pb;
                        bb[1] = *(const uint32_t*)(pb + 8);
                        mma_f16(t[f], a, bb);
                    }
                }
            }
#pragma unroll
            for (int f = 0; f < 8; f++) {
                const int cb = 64 * pass + 8 * f;
                if (cb + 7 >= wlo && cb <= wlo + 78) {
                    __half* p0 = ProdH + qq * 132 + cb + 2 * tg;
                    *(__half2*)p0 = __floats2half2_rn(t[f].x, t[f].y);
                    *(__half2*)(p0 + 8 * 132) = __floats2half2_rn(t[f].z, t[f].w);
                }
            }
        }
        __syncthreads();

        // ---- gather c2p (ProdH[q][q-k+63]); load posQ band ------------------
#pragma unroll
        for (int f = 0; f < 8; f++) {
            const int kk = 8 * f + 2 * tg;
            sfr[f].x += __half2float(ProdH[qq * 132 + qq - kk + 63]);
            sfr[f].y += __half2float(ProdH[qq * 132 + qq - kk + 62]);
            sfr[f].z += __half2float(ProdH[(qq + 8) * 132 + qq - kk + 71]);
            sfr[f].w += __half2float(ProdH[(qq + 8) * 132 + qq - kk + 70]);
        }
        {
            int j = q0 - k0 + 449 + tid;
            j = j < 0 ? 0 : (j > 1023 ? 1023 : j);
            const uint4* bs = (const uint4*)(g_posqh + ((size_t)h * POSJ + j) * HD);
            uint4* bd = (uint4*)(Bandh + tid * 72);
#pragma unroll
            for (int i = 0; i < 8; i++) bd[i] = bs[i];
        }
        __syncthreads();

        // ---- P2C band GEMM (predicated to cols [48-16w, 126-16w]) ----------
#pragma unroll
        for (int pass = 0; pass < 2; pass++) {
            float4 t[8];
#pragma unroll
            for (int f = 0; f < 8; f++) t[f] = make_float4(0.f, 0.f, 0.f, 0.f);
#pragma unroll
            for (int c = 0; c < 4; c++) {
                uint32_t a[4];
                const __half* kr = Ksh + qq * 72 + 16 * c + 2 * tg;
                a[0] = *(const uint32_t*)kr;
                a[1] = *(const uint32_t*)(kr + 8 * 72);
                a[2] = *(const uint32_t*)(kr + 8);
                a[3] = *(const uint32_t*)(kr + 8 * 72 + 8);
#pragma unroll
                for (int f = 0; f < 8; f++) {
                    const int cb = 64 * pass + 8 * f;
                    if (cb + 7 >= 48 - wlo && cb <= 126 - wlo) {
                        uint32_t bb[2];
                        const __half* pb = Bandh + (cb + g) * 72 + 16 * c + 2 * tg;
                        bb[0] = *(const uint32_t*)pb;
                        bb[1] = *(const uint32_t*)(pb + 8);
                        mma_f16(t[f], a, bb);
                    }
                }
            }
#pragma unroll
            for (int f = 0; f < 8; f++) {
                const int cb = 64 * pass + 8 * f;
                if (cb + 7 >= 48 - wlo && cb <= 126 - wlo) {
                    __half* p0 = ProdH + qq * 132 + cb + 2 * tg;
                    *(__half2*)p0 = __floats2half2_rn(t[f].x, t[f].y);
                    *(__half2*)(p0 + 8 * 132) = __floats2half2_rn(t[f].z, t[f].w);
                }
            }
        }
        __syncthreads();

        // ---- gather p2c (ProdH[k][q-k+63]), scale + mask --------------------
#pragma unroll
        for (int f = 0; f < 8; f++) {
            const int kk = 8 * f + 2 * tg;
            sfr[f].x += __half2float(ProdH[kk * 132 + qq - kk + 63]);
            sfr[f].y += __half2float(ProdH[(kk + 1) * 132 + qq - kk + 62]);
            sfr[f].z += __half2float(ProdH[kk * 132 + qq - kk + 71]);
            sfr[f].w += __half2float(ProdH[(kk + 1) * 132 + qq - kk + 70]);
            const float mk0 = Mf[k0 + kk], mk1 = Mf[k0 + kk + 1];
            sfr[f].x = sfr[f].x * SCORE_SCALE + mk0;
            sfr[f].y = sfr[f].y * SCORE_SCALE + mk1;
            sfr[f].z = sfr[f].z * SCORE_SCALE + mk0;
            sfr[f].w = sfr[f].w * SCORE_SCALE + mk1;
        }

        // ---- online softmax -------------------------------------------------
        float r0 = -1e30f, r1 = -1e30f;
#pragma unroll
        for (int f = 0; f < 8; f++) {
            r0 = fmaxf(r0, fmaxf(sfr[f].x, sfr[f].y));
            r1 = fmaxf(r1, fmaxf(sfr[f].z, sfr[f].w));
        }
        r0 = fmaxf(r0, __shfl_xor_sync(0xffffffffu, r0, 1));
        r0 = fmaxf(r0, __shfl_xor_sync(0xffffffffu, r0, 2));
        r1 = fmaxf(r1, __shfl_xor_sync(0xffffffffu, r1, 1));
        r1 = fmaxf(r1, __shfl_xor_sync(0xffffffffu, r1, 2));
        const float nm0 = fmaxf(m0, r0), nm1 = fmaxf(m1, r1);
        const float sc0 = __expf(m0 - nm0), sc1 = __expf(m1 - nm1);
        float rs0 = 0.f, rs1 = 0.f;
#pragma unroll
        for (int f = 0; f < 8; f++) {
            const float px = __expf(sfr[f].x - nm0);
            const float py = __expf(sfr[f].y - nm0);
            const float pz = __expf(sfr[f].z - nm1);
            const float pw = __expf(sfr[f].w - nm1);
            rs0 += px + py; rs1 += pz + pw;
            *(__half2*)(Ps + qq * 72 + 8 * f + 2 * tg) = __floats2half2_rn(px, py);
            *(__half2*)(Ps + (qq + 8) * 72 + 8 * f + 2 * tg) = __floats2half2_rn(pz, pw);
            acc[f].x *= sc0; acc[f].y *= sc0;
            acc[f].z *= sc1; acc[f].w *= sc1;
        }
        rs0 += __shfl_xor_sync(0xffffffffu, rs0, 1);
        rs0 += __shfl_xor_sync(0xffffffffu, rs0, 2);
        rs1 += __shfl_xor_sync(0xffffffffu, rs1, 1);
        rs1 += __shfl_xor_sync(0xffffffffu, rs1, 2);
        l0 = l0 * sc0 + rs0;
        l1 = l1 * sc1 + rs1;
        m0 = nm0; m1 = nm1;

        __syncwarp();

        // ---- PV: acc += P @ V ----------------------------------------------
#pragma unroll
        for (int c = 0; c < 4; c++) {
            uint32_t a[4];
            const __half* pr = Ps + qq * 72 + 16 * c + 2 * tg;
            a[0] = *(const uint32_t*)pr;
            a[1] = *(const uint32_t*)(pr + 8 * 72);
            a[2] = *(const uint32_t*)(pr + 8);
            a[3] = *(const uint32_t*)(pr + 8 * 72 + 8);
#pragma unroll
            for (int f = 0; f < 8; f++) {
                uint32_t bb[2];
                const __half* vb = Vth + (8 * f + g) * 72 + 16 * c + 2 * tg;
                bb[0] = *(const uint32_t*)vb;
                bb[1] = *(const uint32_t*)(vb + 8);
                mma_f16(acc[f], a, bb);
            }
        }
    }

    const float inv0 = 1.0f / l0, inv1 = 1.0f / l1;
    float* orow0 = out + ((size_t)b * S_LEN + q0 + qq) * DIM + h * HD;
    float* orow1 = orow0 + 8 * DIM;
#pragma unroll
    for (int f = 0; f < 8; f++) {
        const int col = 8 * f + 2 * tg;
        *(float2*)(orow0 + col) = make_float2(acc[f].x * inv0, acc[f].y * inv0);
        *(float2*)(orow1 + col) = make_float2(acc[f].z * inv1, acc[f].w * inv1);
    }
}

// ---------------------------------------------------------------------------
extern "C" void kernel_launch(void* const* d_in, const int* in_sizes, int n_in,
                              void* d_out, int out_size)
{
    const float* x    = (const float*)d_in[0];
    const float* rel  = (const float*)d_in[1];
    const float* mask = (const float*)d_in[2];
    const float* Wq   = (const float*)d_in[3];
    const float* bq   = (const float*)d_in[4];
    const float* Wk   = (const float*)d_in[5];
    const float* bk   = (const float*)d_in[6];
    const float* Wv   = (const float*)d_in[7];
    const float* bv   = (const float*)d_in[8];
    float* out = (float*)d_out;

    __half *xh, *wqh, *wkh, *wvh, *relh;
    cudaGetSymbolAddress((void**)&xh, g_xh);
    cudaGetSymbolAddress((void**)&wqh, g_wqh);
    cudaGetSymbolAddress((void**)&wkh, g_wkh);
    cudaGetSymbolAddress((void**)&wvh, g_wvh);
    cudaGetSymbolAddress((void**)&relh, g_relh);

    // pre-convert all GEMM operands to fp16
    cvt_f16<<<2048, 256>>>(x, xh, NB * S_LEN * DIM / 8);
    cvt_f16<<<512, 256>>>(Wq, wqh, DIM * DIM / 8);
    cvt_f16<<<512, 256>>>(Wk, wkh, DIM * DIM / 8);
    cvt_f16<<<512, 256>>>(Wv, wvh, DIM * DIM / 8);
    cvt_f16<<<512, 256>>>(rel, relh, POSJ * DIM / 8);

    // fp16 projections: token (Q,K,V) and pos (posQ, posK)
    proj_h<0><<<dim3(8, 32, 3), dim3(128)>>>(xh, wqh, wkh, wvh, bq, bk, bv);
    proj_h<1><<<dim3(8, 8, 2), dim3(128)>>>(relh, wqh, wkh, wkh, bq, bk, bk);

    // fused fp16 attention (fp16 Prod -> 3 CTAs/SM)
    cudaFuncSetAttribute(attn2_kernel, cudaFuncAttributeMaxDynamicSharedMemorySize,
                         ATTN2_SMEM);
    attn2_kernel<<<dim3(8, BH), dim3(128), ATTN2_SMEM>>>(mask, out);
}

// round 16
// speedup vs baseline: 1.2494x; 1.0117x over previous
#include <cuda_runtime.h>
#include <cuda_fp16.h>
#include <math.h>
#include <stdint.h>

#define S_LEN 512
#define HD    64
#define NH    16
#define NB    8
#define BH    128          // NB*NH
#define DIM   1024
#define POSJ  1024
#define SCORE_SCALE 0.07216878364870322f   // 1/sqrt(64*3)
#define QPITCH 40          // proj smem row pitch in halves (conflict-free)
#define NSTAGE (DIM / 32)  // 32 stages of BK=32 cover the full K reduction

// ---------------- scratch (static device globals; no runtime allocation) ----
__device__ __half g_qh[BH * S_LEN * HD];           // [b,h,s,d]
__device__ __half g_kh[BH * S_LEN * HD];
__device__ __half g_vh[BH * S_LEN * HD];
__device__ __half g_posqh[NH * POSJ * HD];         // [h,j,d]
__device__ __half g_poskh[NH * POSJ * HD];
// pre-converted fp16 inputs
__device__ __half g_xh[NB * S_LEN * DIM];
__device__ __half g_wqh[DIM * DIM];
__device__ __half g_wkh[DIM * DIM];
__device__ __half g_wvh[DIM * DIM];
__device__ __half g_relh[POSJ * DIM];

// ---------------------------------------------------------------------------
// helpers
// ---------------------------------------------------------------------------
__device__ __forceinline__ void mma_f16(float4& c, const uint32_t* a, const uint32_t* b) {
    asm volatile(
        "mma.sync.aligned.m16n8k16.row.col.f32.f16.f16.f32 "
        "{%0,%1,%2,%3}, {%4,%5,%6,%7}, {%8,%9}, {%0,%1,%2,%3};\n"
        : "+f"(c.x), "+f"(c.y), "+f"(c.z), "+f"(c.w)
        : "r"(a[0]), "r"(a[1]), "r"(a[2]), "r"(a[3]), "r"(b[0]), "r"(b[1]));
}
__device__ __forceinline__ uint32_t p2(float a, float b) {
    __half2 h = __floats2half2_rn(a, b);
    return *(uint32_t*)&h;
}
__device__ __forceinline__ void cpa16(uint32_t dst, const void* src) {
    asm volatile("cp.async.ca.shared.global [%0], [%1], 16;" :: "r"(dst), "l"(src) : "memory");
}

// ---------------------------------------------------------------------------
// f32 -> f16 bulk convert (8 floats / thread)
// ---------------------------------------------------------------------------
__global__ void __launch_bounds__(256) cvt_f16(const float* __restrict__ src,
                                               __half* __restrict__ dst, int n8)
{
    const int i = blockIdx.x * blockDim.x + threadIdx.x;
    if (i < n8) {
        const float4 f0 = ((const float4*)src)[2 * i];
        const float4 f1 = ((const float4*)src)[2 * i + 1];
        uint4 u;
        u.x = p2(f0.x, f0.y); u.y = p2(f0.z, f0.w);
        u.z = p2(f1.x, f1.y); u.w = p2(f1.z, f1.w);
        ((uint4*)dst)[i] = u;
    }
}

// ---------------------------------------------------------------------------
// fp16 projection GEMM (fp16 inputs): C = A * W^T + bias -> __half out
// Block 128x128, BK=32 x 32 stages (full K=1024), 128 threads = 4 warps
// (2m x 2n), warp tile 64x64. cp.async double-buffered staging.
// ---------------------------------------------------------------------------
template <int MODE>
__global__ void __launch_bounds__(128) proj_h(const __half* __restrict__ A,
                                              const __half* __restrict__ W0,
                                              const __half* __restrict__ W1,
                                              const __half* __restrict__ W2,
                                              const float* __restrict__ bias0,
                                              const float* __restrict__ bias1,
                                              const float* __restrict__ bias2)
{
    const int z = blockIdx.z;
    const __half* W   = (z == 0) ? W0 : (z == 1) ? W1 : W2;
    const float* bias = (z == 0) ? bias0 : (z == 1) ? bias1 : bias2;
    __half* out = (MODE == 0) ? ((z == 0) ? g_qh : (z == 1) ? g_kh : g_vh)
                              : ((z == 0) ? g_posqh : g_poskh);

    __shared__ __half As[2][128 * QPITCH];
    __shared__ __half Bs[2][128 * QPITCH];

    const int tid  = threadIdx.x;
    const int warp = tid >> 5, lane = tid & 31;
    const int wm = warp >> 1, wn = warp & 1;
    const int g  = lane >> 2, tg = lane & 3;
    const int bm = blockIdx.y, bn = blockIdx.x;

    const __half* Ap = A + (size_t)(bm * 128 + tid) * DIM;
    const __half* Wp = W + (size_t)(bn * 128 + tid) * DIM;
    const uint32_t a0 = (uint32_t)__cvta_generic_to_shared(&As[0][tid * QPITCH]);
    const uint32_t b0 = (uint32_t)__cvta_generic_to_shared(&Bs[0][tid * QPITCH]);
    const uint32_t stage_bytes = 128 * QPITCH * 2;

    float4 c[4][8];
#pragma unroll
    for (int t = 0; t < 4; t++)
#pragma unroll
        for (int f = 0; f < 8; f++) c[t][f] = make_float4(0.f, 0.f, 0.f, 0.f);

    {
#pragma unroll
        for (int ch = 0; ch < 4; ch++) {
            cpa16(a0 + ch * 16, Ap + ch * 8);
            cpa16(b0 + ch * 16, Wp + ch * 8);
        }
        asm volatile("cp.async.commit_group;" ::: "memory");
    }

    for (int s = 0; s < NSTAGE; s++) {
        const int p = s & 1;
        if (s < NSTAGE - 1) {
            const uint32_t ao = a0 + (uint32_t)((s + 1) & 1) * stage_bytes;
            const uint32_t bo = b0 + (uint32_t)((s + 1) & 1) * stage_bytes;
            const __half* as = Ap + (s + 1) * 32;
            const __half* ws = Wp + (s + 1) * 32;
#pragma unroll
            for (int ch = 0; ch < 4; ch++) {
                cpa16(ao + ch * 16, as + ch * 8);
                cpa16(bo + ch * 16, ws + ch * 8);
            }
            asm volatile("cp.async.commit_group;" ::: "memory");
            asm volatile("cp.async.wait_group 1;" ::: "memory");
        } else {
            asm volatile("cp.async.wait_group 0;" ::: "memory");
        }
        __syncthreads();

#pragma unroll
        for (int k16 = 0; k16 < 2; k16++) {
            const int kb = k16 * 16 + 2 * tg;
            uint32_t a[4][4], b[8][2];
#pragma unroll
            for (int t = 0; t < 4; t++) {
                const __half* ar = &As[p][(wm * 64 + t * 16 + g) * QPITCH + kb];
                a[t][0] = *(const uint32_t*)ar;
                a[t][1] = *(const uint32_t*)(ar + 8 * QPITCH);
                a[t][2] = *(const uint32_t*)(ar + 8);
                a[t][3] = *(const uint32_t*)(ar + 8 * QPITCH + 8);
            }
#pragma unroll
            for (int f = 0; f < 8; f++) {
                const __half* br = &Bs[p][(wn * 64 + f * 8 + g) * QPITCH + kb];
                b[f][0] = *(const uint32_t*)br;
                b[f][1] = *(const uint32_t*)(br + 8);
            }
#pragma unroll
            for (int t = 0; t < 4; t++)
#pragma unroll
                for (int f = 0; f < 8; f++)
                    mma_f16(c[t][f], a[t], b[f]);
        }
        __syncthreads();
    }

#pragma unroll
    for (int t = 0; t < 4; t++) {
        const int row0 = bm * 128 + wm * 64 + t * 16 + g;
#pragma unroll
        for (int f = 0; f < 8; f++) {
            const int col = bn * 128 + wn * 64 + f * 8 + 2 * tg;
            const float bb0 = bias[col], bb1 = bias[col + 1];
            __half2 h0 = __floats2half2_rn(c[t][f].x + bb0, c[t][f].y + bb1);
            __half2 h1 = __floats2half2_rn(c[t][f].z + bb0, c[t][f].w + bb1);
            const int h = col >> 6, d = col & 63;
            if (MODE == 0) {
                const int bi0 = row0 >> 9, s0 = row0 & 511;
                *(__half2*)(out + ((size_t)(bi0 * NH + h) * S_LEN + s0) * HD + d) = h0;
                const int r1 = row0 + 8;
                const int bi1 = r1 >> 9, s1 = r1 & 511;
                *(__half2*)(out + ((size_t)(bi1 * NH + h) * S_LEN + s1) * HD + d) = h1;
            } else {
                *(__half2*)(out + ((size_t)h * POSJ + row0) * HD + d) = h0;
                *(__half2*)(out + ((size_t)h * POSJ + row0 + 8) * HD + d) = h1;
            }
        }
    }
}

// ---------------------------------------------------------------------------
// Fused fp16 attention; predicated band GEMMs; fp16 Prod; P kept in
// registers (no Ps smem round-trip). smem = 65,024 B -> 3 CTAs/SM.
// ---------------------------------------------------------------------------
#define SM_QH    0
#define SM_KSH   9216
#define SM_VTH   18432
#define SM_BAND  27648
#define SM_PROD  46080          // __half [64][132] = 16896 B
#define SM_MASK  62976
#define ATTN2_SMEM (62976 + 2048)

__global__ void __launch_bounds__(128, 3) attn2_kernel(const float* __restrict__ mask,
                                                       float* __restrict__ out)
{
    extern __shared__ char smraw[];
    __half* Qh   = (__half*)(smraw + SM_QH);     // [64][72]
    __half* Ksh  = (__half*)(smraw + SM_KSH);    // [64][72]
    __half* Vth  = (__half*)(smraw + SM_VTH);    // [64][72] (V transposed)
    __half* Bandh= (__half*)(smraw + SM_BAND);   // [128][72]
    __half* ProdH= (__half*)(smraw + SM_PROD);   // [64][132] fp16
    float*  Mf   = (float*)(smraw + SM_MASK);    // [512]

    const int tid = threadIdx.x;
    const int w = tid >> 5, lane = tid & 31;
    const int g = lane >> 2, tg = lane & 3;
    const int bh = blockIdx.y;
    const int b = bh >> 4, h = bh & 15;
    const int q0 = blockIdx.x << 6;
    const int wlo = 16 * w;

    {
        const int row = tid >> 1, seg = tid & 1;
        const uint4* src = (const uint4*)(g_qh + ((size_t)bh * S_LEN + q0 + row) * HD + seg * 32);
        uint4* dst = (uint4*)(Qh + row * 72 + seg * 32);
#pragma unroll
        for (int i = 0; i < 4; i++) dst[i] = src[i];
        *(float4*)(Mf + tid * 4) = *(const float4*)(mask + b * S_LEN + tid * 4);
    }

    const int qq = 16 * w + g;

    float4 sfr[8], acc[8];
    float m0 = -1e30f, m1 = -1e30f, l0 = 0.f, l1 = 0.f;
#pragma unroll
    for (int f = 0; f < 8; f++) acc[f] = make_float4(0.f, 0.f, 0.f, 0.f);

    for (int kt = 0; kt < 8; kt++) {
        const int k0 = kt << 6;
        __syncthreads();

        {
            const int row = tid >> 1, seg = tid & 1;
            const uint4* ks = (const uint4*)(g_kh + ((size_t)bh * S_LEN + k0 + row) * HD + seg * 32);
            uint4* kd = (uint4*)(Ksh + row * 72 + seg * 32);
#pragma unroll
            for (int i = 0; i < 4; i++) kd[i] = ks[i];

            const __half2* vs = (const __half2*)(g_vh + ((size_t)bh * S_LEN + k0 + row) * HD + seg * 32);
#pragma unroll
            for (int i = 0; i < 16; i++) {
                __half2 v = vs[i];
                const int d = seg * 32 + 2 * i;
                Vth[d * 72 + row] = __low2half(v);
                Vth[(d + 1) * 72 + row] = __high2half(v);
            }
            int j = q0 - k0 + 449 + tid;
            j = j < 0 ? 0 : (j > 1023 ? 1023 : j);
            const uint4* bs = (const uint4*)(g_poskh + ((size_t)h * POSJ + j) * HD);
            uint4* bd = (uint4*)(Bandh + tid * 72);
#pragma unroll
            for (int i = 0; i < 8; i++) bd[i] = bs[i];
        }
        __syncthreads();

        // ---- S = Q K^T ------------------------------------------------------
#pragma unroll
        for (int f = 0; f < 8; f++) sfr[f] = make_float4(0.f, 0.f, 0.f, 0.f);
#pragma unroll
        for (int c = 0; c < 4; c++) {
            uint32_t a[4];
            const __half* qr = Qh + qq * 72 + 16 * c + 2 * tg;
            a[0] = *(const uint32_t*)qr;
            a[1] = *(const uint32_t*)(qr + 8 * 72);
            a[2] = *(const uint32_t*)(qr + 8);
            a[3] = *(const uint32_t*)(qr + 8 * 72 + 8);
#pragma unroll
            for (int f = 0; f < 8; f++) {
                uint32_t bb[2];
                const __half* kb = Ksh + (8 * f + g) * 72 + 16 * c + 2 * tg;
                bb[0] = *(const uint32_t*)kb;
                bb[1] = *(const uint32_t*)(kb + 8);
                mma_f16(sfr[f], a, bb);
            }
        }

        // ---- C2P band GEMM (predicated to cols [16w, 16w+78]) --------------
#pragma unroll
        for (int pass = 0; pass < 2; pass++) {
            float4 t[8];
#pragma unroll
            for (int f = 0; f < 8; f++) t[f] = make_float4(0.f, 0.f, 0.f, 0.f);
#pragma unroll
            for (int c = 0; c < 4; c++) {
                uint32_t a[4];
                const __half* qr = Qh + qq * 72 + 16 * c + 2 * tg;
                a[0] = *(const uint32_t*)qr;
                a[1] = *(const uint32_t*)(qr + 8 * 72);
                a[2] = *(const uint32_t*)(qr + 8);
                a[3] = *(const uint32_t*)(qr + 8 * 72 + 8);
#pragma unroll
                for (int f = 0; f < 8; f++) {
                    const int cb = 64 * pass + 8 * f;
                    if (cb + 7 >= wlo && cb <= wlo + 78) {
                        uint32_t bb[2];
                        const __half* pb = Bandh + (cb + g) * 72 + 16 * c + 2 * tg;
                        bb[0] = *(const uint32_t*)pb;
                        bb[1] = *(const uint32_t*)(pb + 8);
                        mma_f16(t[f], a, bb);
                    }
                }
            }
#pragma unroll
            for (int f = 0; f < 8; f++) {
                const int cb = 64 * pass + 8 * f;
                if (cb + 7 >= wlo && cb <= wlo + 78) {
                    __half* p0 = ProdH + qq * 132 + cb + 2 * tg;
                    *(__half2*)p0 = __floats2half2_rn(t[f].x, t[f].y);
                    *(__half2*)(p0 + 8 * 132) = __floats2half2_rn(t[f].z, t[f].w);
                }
            }
        }
        __syncthreads();

        // ---- gather c2p (ProdH[q][q-k+63]); load posQ band ------------------
#pragma unroll
        for (int f = 0; f < 8; f++) {
            const int kk = 8 * f + 2 * tg;
            sfr[f].x += __half2float(ProdH[qq * 132 + qq - kk + 63]);
            sfr[f].y += __half2float(ProdH[qq * 132 + qq - kk + 62]);
            sfr[f].z += __half2float(ProdH[(qq + 8) * 132 + qq - kk + 71]);
            sfr[f].w += __half2float(ProdH[(qq + 8) * 132 + qq - kk + 70]);
        }
        {
            int j = q0 - k0 + 449 + tid;
            j = j < 0 ? 0 : (j > 1023 ? 1023 : j);
            const uint4* bs = (const uint4*)(g_posqh + ((size_t)h * POSJ + j) * HD);
            uint4* bd = (uint4*)(Bandh + tid * 72);
#pragma unroll
            for (int i = 0; i < 8; i++) bd[i] = bs[i];
        }
        __syncthreads();

        // ---- P2C band GEMM (predicated to cols [48-16w, 126-16w]) ----------
#pragma unroll
        for (int pass = 0; pass < 2; pass++) {
            float4 t[8];
#pragma unroll
            for (int f = 0; f < 8; f++) t[f] = make_float4(0.f, 0.f, 0.f, 0.f);
#pragma unroll
            for (int c = 0; c < 4; c++) {
                uint32_t a[4];
                const __half* kr = Ksh + qq * 72 + 16 * c + 2 * tg;
                a[0] = *(const uint32_t*)kr;
                a[1] = *(const uint32_t*)(kr + 8 * 72);
                a[2] = *(const uint32_t*)(kr + 8);
                a[3] = *(const uint32_t*)(kr + 8 * 72 + 8);
#pragma unroll
                for (int f = 0; f < 8; f++) {
                    const int cb = 64 * pass + 8 * f;
                    if (cb + 7 >= 48 - wlo && cb <= 126 - wlo) {
                        uint32_t bb[2];
                        const __half* pb = Bandh + (cb + g) * 72 + 16 * c + 2 * tg;
                        bb[0] = *(const uint32_t*)pb;
                        bb[1] = *(const uint32_t*)(pb + 8);
                        mma_f16(t[f], a, bb);
                    }
                }
            }
#pragma unroll
            for (int f = 0; f < 8; f++) {
                const int cb = 64 * pass + 8 * f;
                if (cb + 7 >= 48 - wlo && cb <= 126 - wlo) {
                    __half* p0 = ProdH + qq * 132 + cb + 2 * tg;
                    *(__half2*)p0 = __floats2half2_rn(t[f].x, t[f].y);
                    *(__half2*)(p0 + 8 * 132) = __floats2half2_rn(t[f].z, t[f].w);
                }
            }
        }
        __syncthreads();

        // ---- gather p2c (ProdH[k][q-k+63]), scale + mask --------------------
#pragma unroll
        for (int f = 0; f < 8; f++) {
            const int kk = 8 * f + 2 * tg;
            sfr[f].x += __half2float(ProdH[kk * 132 + qq - kk + 63]);
            sfr[f].y += __half2float(ProdH[(kk + 1) * 132 + qq - kk + 62]);
            sfr[f].z += __half2float(ProdH[kk * 132 + qq - kk + 71]);
            sfr[f].w += __half2float(ProdH[(kk + 1) * 132 + qq - kk + 70]);
            const float mk0 = Mf[k0 + kk], mk1 = Mf[k0 + kk + 1];
            sfr[f].x = sfr[f].x * SCORE_SCALE + mk0;
            sfr[f].y = sfr[f].y * SCORE_SCALE + mk1;
            sfr[f].z = sfr[f].z * SCORE_SCALE + mk0;
            sfr[f].w = sfr[f].w * SCORE_SCALE + mk1;
        }

        // ---- online softmax; pack P fragments in registers ------------------
        float r0 = -1e30f, r1 = -1e30f;
#pragma unroll
        for (int f = 0; f < 8; f++) {
            r0 = fmaxf(r0, fmaxf(sfr[f].x, sfr[f].y));
            r1 = fmaxf(r1, fmaxf(sfr[f].z, sfr[f].w));
        }
        r0 = fmaxf(r0, __shfl_xor_sync(0xffffffffu, r0, 1));
        r0 = fmaxf(r0, __shfl_xor_sync(0xffffffffu, r0, 2));
        r1 = fmaxf(r1, __shfl_xor_sync(0xffffffffu, r1, 1));
        r1 = fmaxf(r1, __shfl_xor_sync(0xffffffffu, r1, 2));
        const float nm0 = fmaxf(m0, r0), nm1 = fmaxf(m1, r1);
        const float sc0 = __expf(m0 - nm0), sc1 = __expf(m1 - nm1);
        float rs0 = 0.f, rs1 = 0.f;
        uint32_t ph0[8], ph1[8];   // P fragments: rows qq / qq+8
#pragma unroll
        for (int f = 0; f < 8; f++) {
            const float px = __expf(sfr[f].x - nm0);
            const float py = __expf(sfr[f].y - nm0);
            const float pz = __expf(sfr[f].z - nm1);
            const float pw = __expf(sfr[f].w - nm1);
            rs0 += px + py; rs1 += pz + pw;
            ph0[f] = p2(px, py);
            ph1[f] = p2(pz, pw);
            acc[f].x *= sc0; acc[f].y *= sc0;
            acc[f].z *= sc1; acc[f].w *= sc1;
        }
        rs0 += __shfl_xor_sync(0xffffffffu, rs0, 1);
        rs0 += __shfl_xor_sync(0xffffffffu, rs0, 2);
        rs1 += __shfl_xor_sync(0xffffffffu, rs1, 1);
        rs1 += __shfl_xor_sync(0xffffffffu, rs1, 2);
        l0 = l0 * sc0 + rs0;
        l1 = l1 * sc1 + rs1;
        m0 = nm0; m1 = nm1;

        // ---- PV: acc += P @ V  (P fragments direct from registers) ---------
#pragma unroll
        for (int c = 0; c < 4; c++) {
            uint32_t a[4];
            a[0] = ph0[2 * c];
            a[1] = ph1[2 * c];
            a[2] = ph0[2 * c + 1];
            a[3] = ph1[2 * c + 1];
#pragma unroll
            for (int f = 0; f < 8; f++) {
                uint32_t bb[2];
                const __half* vb = Vth + (8 * f + g) * 72 + 16 * c + 2 * tg;
                bb[0] = *(const uint32_t*)vb;
                bb[1] = *(const uint32_t*)(vb + 8);
                mma_f16(acc[f], a, bb);
            }
        }
    }

    const float inv0 = 1.0f / l0, inv1 = 1.0f / l1;
    float* orow0 = out + ((size_t)b * S_LEN + q0 + qq) * DIM + h * HD;
    float* orow1 = orow0 + 8 * DIM;
#pragma unroll
    for (int f = 0; f < 8; f++) {
        const int col = 8 * f + 2 * tg;
        *(float2*)(orow0 + col) = make_float2(acc[f].x * inv0, acc[f].y * inv0);
        *(float2*)(orow1 + col) = make_float2(acc[f].z * inv1, acc[f].w * inv1);
    }
}

// ---------------------------------------------------------------------------
extern "C" void kernel_launch(void* const* d_in, const int* in_sizes, int n_in,
                              void* d_out, int out_size)
{
    const float* x    = (const float*)d_in[0];
    const float* rel  = (const float*)d_in[1];
    const float* mask = (const float*)d_in[2];
    const float* Wq   = (const float*)d_in[3];
    const float* bq   = (const float*)d_in[4];
    const float* Wk   = (const float*)d_in[5];
    const float* bk   = (const float*)d_in[6];
    const float* Wv   = (const float*)d_in[7];
    const float* bv   = (const float*)d_in[8];
    float* out = (float*)d_out;

    __half *xh, *wqh, *wkh, *wvh, *relh;
    cudaGetSymbolAddress((void**)&xh, g_xh);
    cudaGetSymbolAddress((void**)&wqh, g_wqh);
    cudaGetSymbolAddress((void**)&wkh, g_wkh);
    cudaGetSymbolAddress((void**)&wvh, g_wvh);
    cudaGetSymbolAddress((void**)&relh, g_relh);

    // pre-convert all GEMM operands to fp16
    cvt_f16<<<2048, 256>>>(x, xh, NB * S_LEN * DIM / 8);
    cvt_f16<<<512, 256>>>(Wq, wqh, DIM * DIM / 8);
    cvt_f16<<<512, 256>>>(Wk, wkh, DIM * DIM / 8);
    cvt_f16<<<512, 256>>>(Wv, wvh, DIM * DIM / 8);
    cvt_f16<<<512, 256>>>(rel, relh, POSJ * DIM / 8);

    // fp16 projections: token (Q,K,V) and pos (posQ, posK)
    proj_h<0><<<dim3(8, 32, 3), dim3(128)>>>(xh, wqh, wkh, wvh, bq, bk, bv);
    proj_h<1><<<dim3(8, 8, 2), dim3(128)>>>(relh, wqh, wkh, wkh, bq, bk, bk);

    // fused fp16 attention (register P fragments, fp16 Prod, 3 CTAs/SM)
    cudaFuncSetAttribute(attn2_kernel, cudaFuncAttributeMaxDynamicSharedMemorySize,
                         ATTN2_SMEM);
    attn2_kernel<<<dim3(8, BH), dim3(128), ATTN2_SMEM>>>(mask, out);
}